// round 1
// baseline (speedup 1.0000x reference)
#include <cuda_runtime.h>
#include <math.h>

// Problem dims (fixed by the dataset)
#define BB   4
#define DD   512
#define LL   4096
#define NC1  1168
#define NLBL 8929

#define SCALE_INV 0.044194173824159216f  // 1/sqrt(512)

// ---------------- device scratch (no mallocs allowed) ----------------
__device__ float g_K  [(size_t)BB * LL * DD];     // [B, L, d]
__device__ float g_V  [(size_t)BB * LL * DD];     // [B, L, d]
__device__ float g_E1 [(size_t)BB * NC1 * LL];    // [B, C1, L]
__device__ float g_C1 [(size_t)BB * NC1 * DD];    // [B, C1, d]
__device__ float g_Q2b[(size_t)BB * NLBL * DD];   // [B, Lbl, d]

// =====================================================================
// KV projection: Out[b,l,dd] = elu( sum_f H[b,f,l] * W[dd,f] + bias[dd] )
// H is [B, d, L] (f-major rows, l contiguous). 128x128x16 tiling.
// =====================================================================
__global__ void __launch_bounds__(256) gemm_tn_bias_elu(
    const float* __restrict__ Hb, const float* __restrict__ W,
    const float* __restrict__ bias, float* __restrict__ Out)
{
    const float* A = Hb + (size_t)blockIdx.z * DD * LL;   // H[b]
    float* C = Out + (size_t)blockIdx.z * LL * DD;
    const int m0 = blockIdx.y * 128;   // l tile
    const int n0 = blockIdx.x * 128;   // dd tile

    __shared__ float As[16][132];
    __shared__ float Bs[16][132];

    const int tid = threadIdx.x;
    const int tx = tid & 15, ty = tid >> 4;
    float acc[8][8] = {};

    const int af  = tid >> 4;          // 0..15 (k row of A tile)
    const int alq = (tid & 15) * 8;    // l offset
    const int br  = tid >> 1;          // 0..127 (dd row of W tile)
    const int bk  = (tid & 1) * 8;     // k offset

    for (int k0 = 0; k0 < DD; k0 += 16) {
        const float* pa = A + (size_t)(k0 + af) * LL + m0 + alq;
        float4 a0 = *(const float4*)pa;
        float4 a1 = *(const float4*)(pa + 4);
        *(float4*)&As[af][alq]     = a0;
        *(float4*)&As[af][alq + 4] = a1;

        const float* pb = W + (size_t)(n0 + br) * DD + k0 + bk;
        float4 b0 = *(const float4*)pb;
        float4 b1 = *(const float4*)(pb + 4);
        Bs[bk + 0][br] = b0.x; Bs[bk + 1][br] = b0.y;
        Bs[bk + 2][br] = b0.z; Bs[bk + 3][br] = b0.w;
        Bs[bk + 4][br] = b1.x; Bs[bk + 5][br] = b1.y;
        Bs[bk + 6][br] = b1.z; Bs[bk + 7][br] = b1.w;
        __syncthreads();

        #pragma unroll
        for (int k = 0; k < 16; ++k) {
            float a[8], b[8];
            *(float4*)&a[0] = *(const float4*)&As[k][ty * 8];
            *(float4*)&a[4] = *(const float4*)&As[k][ty * 8 + 4];
            *(float4*)&b[0] = *(const float4*)&Bs[k][tx * 8];
            *(float4*)&b[4] = *(const float4*)&Bs[k][tx * 8 + 4];
            #pragma unroll
            for (int i = 0; i < 8; ++i)
                #pragma unroll
                for (int j = 0; j < 8; ++j)
                    acc[i][j] += a[i] * b[j];
        }
        __syncthreads();
    }

    float bv[8];
    #pragma unroll
    for (int j = 0; j < 8; ++j) bv[j] = bias[n0 + tx * 8 + j];

    #pragma unroll
    for (int i = 0; i < 8; ++i) {
        const int m = m0 + ty * 8 + i;
        float* crow = C + (size_t)m * DD + n0 + tx * 8;
        #pragma unroll
        for (int j = 0; j < 8; ++j) {
            float r = acc[i][j] + bv[j];
            crow[j] = (r > 0.0f) ? r : expm1f(r);
        }
    }
}

// =====================================================================
// NT GEMM: C[m,n] = alpha * sum_k A[m,k] * B[n,k]   (both row-major, K inner)
// =====================================================================
__global__ void __launch_bounds__(256) gemm_nt(
    const float* __restrict__ Ab, const float* __restrict__ Bb,
    float* __restrict__ Cb, int M, int N, int Kd,
    size_t sA, size_t sB, size_t sC, float alpha)
{
    const float* A = Ab + (size_t)blockIdx.z * sA;
    const float* B = Bb + (size_t)blockIdx.z * sB;
    float* C = Cb + (size_t)blockIdx.z * sC;
    const int m0 = blockIdx.y * 128, n0 = blockIdx.x * 128;

    __shared__ float As[16][132];
    __shared__ float Bs[16][132];

    const int tid = threadIdx.x;
    const int tx = tid & 15, ty = tid >> 4;
    float acc[8][8] = {};

    const int lr = tid >> 1;        // 0..127 tile row
    const int lk = (tid & 1) * 8;   // 0 or 8

    for (int k0 = 0; k0 < Kd; k0 += 16) {
        float4 a0 = {0,0,0,0}, a1 = {0,0,0,0};
        if (m0 + lr < M) {
            const float* p = A + (size_t)(m0 + lr) * Kd + k0 + lk;
            a0 = *(const float4*)p; a1 = *(const float4*)(p + 4);
        }
        As[lk + 0][lr] = a0.x; As[lk + 1][lr] = a0.y;
        As[lk + 2][lr] = a0.z; As[lk + 3][lr] = a0.w;
        As[lk + 4][lr] = a1.x; As[lk + 5][lr] = a1.y;
        As[lk + 6][lr] = a1.z; As[lk + 7][lr] = a1.w;

        float4 b0 = {0,0,0,0}, b1 = {0,0,0,0};
        if (n0 + lr < N) {
            const float* p = B + (size_t)(n0 + lr) * Kd + k0 + lk;
            b0 = *(const float4*)p; b1 = *(const float4*)(p + 4);
        }
        Bs[lk + 0][lr] = b0.x; Bs[lk + 1][lr] = b0.y;
        Bs[lk + 2][lr] = b0.z; Bs[lk + 3][lr] = b0.w;
        Bs[lk + 4][lr] = b1.x; Bs[lk + 5][lr] = b1.y;
        Bs[lk + 6][lr] = b1.z; Bs[lk + 7][lr] = b1.w;
        __syncthreads();

        #pragma unroll
        for (int k = 0; k < 16; ++k) {
            float a[8], b[8];
            *(float4*)&a[0] = *(const float4*)&As[k][ty * 8];
            *(float4*)&a[4] = *(const float4*)&As[k][ty * 8 + 4];
            *(float4*)&b[0] = *(const float4*)&Bs[k][tx * 8];
            *(float4*)&b[4] = *(const float4*)&Bs[k][tx * 8 + 4];
            #pragma unroll
            for (int i = 0; i < 8; ++i)
                #pragma unroll
                for (int j = 0; j < 8; ++j)
                    acc[i][j] += a[i] * b[j];
        }
        __syncthreads();
    }

    #pragma unroll
    for (int i = 0; i < 8; ++i) {
        const int m = m0 + ty * 8 + i;
        if (m >= M) continue;
        #pragma unroll
        for (int j = 0; j < 8; ++j) {
            const int n = n0 + tx * 8 + j;
            if (n < N) C[(size_t)m * N + n] = alpha * acc[i][j];
        }
    }
}

// =====================================================================
// NN GEMM: C[m,n] = sum_k A[m,k] * B[k,n]   (row-major)
// =====================================================================
__global__ void __launch_bounds__(256) gemm_nn(
    const float* __restrict__ Ab, const float* __restrict__ Bb,
    float* __restrict__ Cb, int M, int N, int Kd,
    size_t sA, size_t sB, size_t sC)
{
    const float* A = Ab + (size_t)blockIdx.z * sA;
    const float* B = Bb + (size_t)blockIdx.z * sB;
    float* C = Cb + (size_t)blockIdx.z * sC;
    const int m0 = blockIdx.y * 128, n0 = blockIdx.x * 128;

    __shared__ float As[16][132];
    __shared__ float Bs[16][132];

    const int tid = threadIdx.x;
    const int tx = tid & 15, ty = tid >> 4;
    float acc[8][8] = {};

    const int lr = tid >> 1;          // A tile row 0..127
    const int lk = (tid & 1) * 8;
    const int bkr = tid >> 4;         // B tile k-row 0..15
    const int bn  = (tid & 15) * 8;   // B tile n offset

    for (int k0 = 0; k0 < Kd; k0 += 16) {
        float4 a0 = {0,0,0,0}, a1 = {0,0,0,0};
        if (m0 + lr < M) {
            const float* p = A + (size_t)(m0 + lr) * Kd + k0 + lk;
            a0 = *(const float4*)p; a1 = *(const float4*)(p + 4);
        }
        As[lk + 0][lr] = a0.x; As[lk + 1][lr] = a0.y;
        As[lk + 2][lr] = a0.z; As[lk + 3][lr] = a0.w;
        As[lk + 4][lr] = a1.x; As[lk + 5][lr] = a1.y;
        As[lk + 6][lr] = a1.z; As[lk + 7][lr] = a1.w;

        float4 b0 = {0,0,0,0}, b1 = {0,0,0,0};
        if (n0 + bn < N) {
            const float* p = B + (size_t)(k0 + bkr) * N + n0 + bn;
            b0 = *(const float4*)p; b1 = *(const float4*)(p + 4);
        }
        *(float4*)&Bs[bkr][bn]     = b0;
        *(float4*)&Bs[bkr][bn + 4] = b1;
        __syncthreads();

        #pragma unroll
        for (int k = 0; k < 16; ++k) {
            float a[8], b[8];
            *(float4*)&a[0] = *(const float4*)&As[k][ty * 8];
            *(float4*)&a[4] = *(const float4*)&As[k][ty * 8 + 4];
            *(float4*)&b[0] = *(const float4*)&Bs[k][tx * 8];
            *(float4*)&b[4] = *(const float4*)&Bs[k][tx * 8 + 4];
            #pragma unroll
            for (int i = 0; i < 8; ++i)
                #pragma unroll
                for (int j = 0; j < 8; ++j)
                    acc[i][j] += a[i] * b[j];
        }
        __syncthreads();
    }

    #pragma unroll
    for (int i = 0; i < 8; ++i) {
        const int m = m0 + ty * 8 + i;
        if (m >= M) continue;
        #pragma unroll
        for (int j = 0; j < 8; ++j) {
            const int n = n0 + tx * 8 + j;
            if (n < N) C[(size_t)m * N + n] = acc[i][j];
        }
    }
}

// =====================================================================
// Row softmax, fixed row length 4096, 256 threads (16 elems/thread)
// =====================================================================
__global__ void __launch_bounds__(256) softmax4096(float* __restrict__ X)
{
    float* x = X + (size_t)blockIdx.x * 4096;
    const int tid = threadIdx.x;
    const int lane = tid & 31, wid = tid >> 5;
    __shared__ float red[32];

    float4 v[4];
    float mx = -1e30f;
    #pragma unroll
    for (int i = 0; i < 4; ++i) {
        v[i] = *(const float4*)&x[(i * 256 + tid) * 4];
        mx = fmaxf(mx, fmaxf(fmaxf(v[i].x, v[i].y), fmaxf(v[i].z, v[i].w)));
    }
    #pragma unroll
    for (int o = 16; o > 0; o >>= 1) mx = fmaxf(mx, __shfl_xor_sync(0xffffffffu, mx, o));
    if (lane == 0) red[wid] = mx;
    __syncthreads();
    if (wid == 0) {
        float m = (lane < 8) ? red[lane] : -1e30f;
        #pragma unroll
        for (int o = 4; o > 0; o >>= 1) m = fmaxf(m, __shfl_xor_sync(0xffffffffu, m, o));
        if (lane == 0) red[0] = m;
    }
    __syncthreads();
    mx = red[0];

    float sum = 0.0f;
    #pragma unroll
    for (int i = 0; i < 4; ++i) {
        v[i].x = __expf(v[i].x - mx);
        v[i].y = __expf(v[i].y - mx);
        v[i].z = __expf(v[i].z - mx);
        v[i].w = __expf(v[i].w - mx);
        sum += v[i].x + v[i].y + v[i].z + v[i].w;
    }
    #pragma unroll
    for (int o = 16; o > 0; o >>= 1) sum += __shfl_xor_sync(0xffffffffu, sum, o);
    if (lane == 0) red[16 + wid] = sum;
    __syncthreads();
    if (wid == 0) {
        float s = (lane < 8) ? red[16 + lane] : 0.0f;
        #pragma unroll
        for (int o = 4; o > 0; o >>= 1) s += __shfl_xor_sync(0xffffffffu, s, o);
        if (lane == 0) red[16] = s;
    }
    __syncthreads();
    const float inv = 1.0f / red[16];

    #pragma unroll
    for (int i = 0; i < 4; ++i) {
        v[i].x *= inv; v[i].y *= inv; v[i].z *= inv; v[i].w *= inv;
        *(float4*)&x[(i * 256 + tid) * 4] = v[i];
    }
}

// =====================================================================
// Q2b[b,n,:] = Q2[n,:] + C1[b, map[n], :]
// =====================================================================
__global__ void __launch_bounds__(128) q2b_kernel(
    const float* __restrict__ Q2, const int* __restrict__ cmap)
{
    const int n = blockIdx.x;
    const int b = blockIdx.y;
    const int c = cmap[n];
    const float4* q  = (const float4*)(Q2 + (size_t)n * DD);
    const float4* c1 = (const float4*)(g_C1 + ((size_t)b * NC1 + c) * DD);
    float4* out = (float4*)(g_Q2b + ((size_t)b * NLBL + n) * DD);
    const int i = threadIdx.x;  // 128 threads, DD/4 = 128 float4s
    float4 a = q[i], bb = c1[i];
    out[i] = make_float4(a.x + bb.x, a.y + bb.y, a.z + bb.z, a.w + bb.w);
}

// =====================================================================
// host
// =====================================================================
extern "C" void kernel_launch(void* const* d_in, const int* in_sizes, int n_in,
                              void* d_out, int out_size)
{
    const float* H    = (const float*)d_in[0];
    const float* Wk   = (const float*)d_in[1];
    const float* bk   = (const float*)d_in[2];
    const float* Wv   = (const float*)d_in[3];
    const float* bv   = (const float*)d_in[4];
    const float* Q1   = (const float*)d_in[5];
    const float* Q2   = (const float*)d_in[6];
    const int*   cmap = (const int*)d_in[7];

    float* C2 = (float*)d_out;                            // [B, Lbl, d]
    float* A2 = C2 + (size_t)BB * NLBL * DD;              // [B, Lbl, L]

    float *pK, *pV, *pE1, *pC1, *pQ2b;
    cudaGetSymbolAddress((void**)&pK,   g_K);
    cudaGetSymbolAddress((void**)&pV,   g_V);
    cudaGetSymbolAddress((void**)&pE1,  g_E1);
    cudaGetSymbolAddress((void**)&pC1,  g_C1);
    cudaGetSymbolAddress((void**)&pQ2b, g_Q2b);

    const dim3 blk(256);

    // K = elu(H^T Wk^T + bk), V = elu(H^T Wv^T + bv)
    dim3 gkv(DD / 128, LL / 128, BB);
    gemm_tn_bias_elu<<<gkv, blk>>>(H, Wk, bk, pK);
    gemm_tn_bias_elu<<<gkv, blk>>>(H, Wv, bv, pV);

    // E1 = Q1 K^T / SCALE  -> [B, C1, L]
    gemm_nt<<<dim3(LL / 128, (NC1 + 127) / 128, BB), blk>>>(
        Q1, pK, pE1, NC1, LL, DD,
        (size_t)0, (size_t)LL * DD, (size_t)NC1 * LL, SCALE_INV);

    // softmax over L
    softmax4096<<<BB * NC1, 256>>>(pE1);

    // C1 = A1 V  -> [B, C1, d]
    gemm_nn<<<dim3(DD / 128, (NC1 + 127) / 128, BB), blk>>>(
        pE1, pV, pC1, NC1, DD, LL,
        (size_t)NC1 * LL, (size_t)LL * DD, (size_t)NC1 * DD);

    // Q2b = Q2 + C1[:, map, :]
    q2b_kernel<<<dim3(NLBL, BB), 128>>>(Q2, cmap);

    // E2 = Q2b K^T / SCALE  -> written directly into A2 output region
    gemm_nt<<<dim3(LL / 128, (NLBL + 127) / 128, BB), blk>>>(
        pQ2b, pK, A2, NLBL, LL, DD,
        (size_t)NLBL * DD, (size_t)LL * DD, (size_t)NLBL * LL, SCALE_INV);

    // softmax over L (in place in output)
    softmax4096<<<BB * NLBL, 256>>>(A2);

    // C2 = A2 V  -> [B, Lbl, d]
    gemm_nn<<<dim3(DD / 128, (NLBL + 127) / 128, BB), blk>>>(
        A2, pV, C2, NLBL, DD, LL,
        (size_t)NLBL * LL, (size_t)LL * DD, (size_t)NLBL * DD);
}

// round 4
// speedup vs baseline: 1.5797x; 1.5797x over previous
#include <cuda_runtime.h>
#include <math.h>
#include <stdint.h>

// Problem dims (fixed)
#define BB   4
#define DD   512
#define LL   4096
#define NC1  1168
#define NLBL 8929

#define SCALE_INV 0.044194173824159216f  // 1/sqrt(512)

// Block tile 128x128, K-chunk 32, 256 threads (8 warps: 4m x 2n, warp tile 32x64)
#define KC 32

// smem: double-buffered A (128x32 f32 = 16KB) and B (16KB)
#define SA0 0
#define SA1 16384
#define SB0 32768
#define SB1 49152
#define SM_TOTAL 65536

// ---------------- device scratch ----------------
__device__ float g_Ht [(size_t)BB * LL * DD];     // [B, L, d]
__device__ float g_K  [(size_t)BB * LL * DD];     // [B, L, d]
__device__ float g_Vt [(size_t)BB * DD * LL];     // [B, d, L]
__device__ float g_E1 [(size_t)BB * NC1 * LL];    // [B, C1, L]
__device__ float g_C1 [(size_t)BB * NC1 * DD];    // [B, C1, d]
__device__ float g_Q2b[(size_t)BB * NLBL * DD];   // [B, Lbl, d]

// ---------------- helpers ----------------
__device__ __forceinline__ uint32_t smem_u32(const void* p) {
    uint32_t a;
    asm("{ .reg .u64 t; cvta.to.shared.u64 t, %1; cvt.u32.u64 %0, t; }" : "=r"(a) : "l"(p));
    return a;
}
__device__ __forceinline__ void cp16(uint32_t dst, const float* src, bool pred) {
    int sz = pred ? 16 : 0;
    asm volatile("cp.async.cg.shared.global [%0], [%1], 16, %2;"
                 :: "r"(dst), "l"(src), "r"(sz));
}
__device__ __forceinline__ void cp_commit() {
    asm volatile("cp.async.commit_group;" ::: "memory");
}
__device__ __forceinline__ void ldsm4(uint32_t* r, uint32_t addr) {
    asm volatile("ldmatrix.sync.aligned.m8n8.x4.shared.b16 {%0,%1,%2,%3}, [%4];"
                 : "=r"(r[0]), "=r"(r[1]), "=r"(r[2]), "=r"(r[3]) : "r"(addr));
}
__device__ __forceinline__ void mma_tf32(float* d, const uint32_t* a, const uint32_t* b) {
    asm volatile(
        "mma.sync.aligned.m16n8k8.row.col.f32.tf32.tf32.f32 "
        "{%0,%1,%2,%3}, {%4,%5,%6,%7}, {%8,%9}, {%0,%1,%2,%3};"
        : "+f"(d[0]), "+f"(d[1]), "+f"(d[2]), "+f"(d[3])
        : "r"(a[0]), "r"(a[1]), "r"(a[2]), "r"(a[3]), "r"(b[0]), "r"(b[1]));
}
// 3xTF32 split: x = hi + lo (both exactly representable in tf32)
__device__ __forceinline__ void split_tf32(uint32_t x, uint32_t& hi, uint32_t& lo) {
    float xf = __uint_as_float(x);
    asm("cvt.rna.tf32.f32 %0, %1;" : "=r"(hi) : "f"(xf));
    float rf = xf - __uint_as_float(hi);
    asm("cvt.rna.tf32.f32 %0, %1;" : "=r"(lo) : "f"(rf));
}
__device__ __forceinline__ float eluf(float x) { return x > 0.0f ? x : expm1f(x); }

// =====================================================================
// 3xTF32 mma.sync NT GEMM: D[m,n] = sum_k A[m,k]*B[n,k]  (~fp32 accuracy)
// A: [M, K] lda,  B: [N, K] ldb
// mode 0: out[m*ldc+n] = elu(acc + bias[n])
// mode 1: out[n*ldc+m] = elu(acc + bias[n])   (transposed store)
// mode 2: out[m*ldc+n] = alpha * acc
// N, K multiples of 128 / 32; M may be ragged.
// =====================================================================
__global__ void __launch_bounds__(256, 2) gemm_tc(
    const float* __restrict__ Ab, const float* __restrict__ Bb,
    float* __restrict__ Cb, const float* __restrict__ bias,
    int M, int K, int lda, int ldb, int ldc,
    size_t sA, size_t sB, size_t sC, float alpha, int mode)
{
    extern __shared__ char smem[];
    const uint32_t sbase = smem_u32(smem);

    const int tid  = threadIdx.x;
    const int wid  = tid >> 5;
    const int lane = tid & 31;
    const int g    = lane >> 3;    // ldmatrix provider group 0..3
    const int r    = lane & 7;     // row within group
    const int warp_m = wid & 3;    // 0..3  (32 rows each)
    const int warp_n = wid >> 2;   // 0..1  (64 cols each)

    const float* A = Ab + (size_t)blockIdx.z * sA;
    const float* B = Bb + (size_t)blockIdx.z * sB;
    float*       C = Cb + (size_t)blockIdx.z * sC;
    const int m0 = blockIdx.y * 128;
    const int n0 = blockIdx.x * 128;

    // ldmatrix source offsets (SW128 swizzle = XOR of bits 4-6 with row&7)
    const uint32_t sw  = (uint32_t)r * 16;
    uint32_t aRow[2], bRow[4];
    #pragma unroll
    for (int mt = 0; mt < 2; ++mt)
        aRow[mt] = (uint32_t)(warp_m * 32 + mt * 16 + (g & 1) * 8 + r) * 128;
    const uint32_t akb = (uint32_t)(g >> 1) * 16;
    #pragma unroll
    for (int p = 0; p < 4; ++p)
        bRow[p] = (uint32_t)(warp_n * 64 + (p * 2 + (g >> 1)) * 8 + r) * 128;
    const uint32_t bkb = (uint32_t)(g & 1) * 16;

    // cp.async staging
    const int srow = tid >> 3;
    const int sc4  = tid & 7;
    const uint32_t sdst_off = (uint32_t)(sc4 * 16);

    float acc[2][8][4];
    #pragma unroll
    for (int mt = 0; mt < 2; ++mt)
        #pragma unroll
        for (int nt = 0; nt < 8; ++nt)
            #pragma unroll
            for (int c = 0; c < 4; ++c) acc[mt][nt][c] = 0.0f;

    const int nc = K >> 5;

    // ---- stage chunk 0 ----
    {
        const uint32_t ab = sbase + SA0, bb = sbase + SB0;
        #pragma unroll
        for (int q = 0; q < 4; ++q) {
            int row = srow + q * 32;
            int m = m0 + row;
            const float* src = A + (size_t)(m < M ? m : 0) * lda + sc4 * 4;
            cp16(ab + (uint32_t)row * 128 + (sdst_off ^ ((row & 7) * 16)), src, m < M);
        }
        #pragma unroll
        for (int q = 0; q < 4; ++q) {
            int row = srow + q * 32;
            const float* src = B + (size_t)(n0 + row) * ldb + sc4 * 4;
            cp16(bb + (uint32_t)row * 128 + (sdst_off ^ ((row & 7) * 16)), src, true);
        }
        cp_commit();
    }

    for (int i = 0; i < nc; ++i) {
        const int b = i & 1;
        if (i + 1 < nc) {
            const int k0 = (i + 1) * KC;
            const uint32_t ab = sbase + (b ? SA0 : SA1);
            const uint32_t bb = sbase + (b ? SB0 : SB1);
            #pragma unroll
            for (int q = 0; q < 4; ++q) {
                int row = srow + q * 32;
                int m = m0 + row;
                const float* src = A + (size_t)(m < M ? m : 0) * lda + k0 + sc4 * 4;
                cp16(ab + (uint32_t)row * 128 + (sdst_off ^ ((row & 7) * 16)), src, m < M);
            }
            #pragma unroll
            for (int q = 0; q < 4; ++q) {
                int row = srow + q * 32;
                const float* src = B + (size_t)(n0 + row) * ldb + k0 + sc4 * 4;
                cp16(bb + (uint32_t)row * 128 + (sdst_off ^ ((row & 7) * 16)), src, true);
            }
            cp_commit();
            asm volatile("cp.async.wait_group 1;" ::: "memory");
        } else {
            asm volatile("cp.async.wait_group 0;" ::: "memory");
        }
        __syncthreads();

        const uint32_t abase = sbase + (b ? SA1 : SA0);
        const uint32_t bbase = sbase + (b ? SB1 : SB0);
        #pragma unroll
        for (int ks = 0; ks < 4; ++ks) {
            const uint32_t kb = (uint32_t)ks * 32;
            uint32_t araw[2][4], ah[2][4], al[2][4];
            ldsm4(araw[0], abase + aRow[0] + ((kb + akb) ^ sw));
            ldsm4(araw[1], abase + aRow[1] + ((kb + akb) ^ sw));
            #pragma unroll
            for (int mt = 0; mt < 2; ++mt)
                #pragma unroll
                for (int e = 0; e < 4; ++e)
                    split_tf32(araw[mt][e], ah[mt][e], al[mt][e]);

            #pragma unroll
            for (int p = 0; p < 4; ++p) {
                uint32_t braw[4], bh[4], bl[4];
                ldsm4(braw, bbase + bRow[p] + ((kb + bkb) ^ sw));
                #pragma unroll
                for (int e = 0; e < 4; ++e) split_tf32(braw[e], bh[e], bl[e]);
                #pragma unroll
                for (int h = 0; h < 2; ++h) {
                    const int nt = p * 2 + h;
                    #pragma unroll
                    for (int mt = 0; mt < 2; ++mt) {
                        mma_tf32(acc[mt][nt], ah[mt], &bh[h * 2]);   // hi*hi
                        mma_tf32(acc[mt][nt], ah[mt], &bl[h * 2]);   // hi*lo
                        mma_tf32(acc[mt][nt], al[mt], &bh[h * 2]);   // lo*hi
                    }
                }
            }
        }
        __syncthreads();
    }

    // ---- epilogue ----
    const int rq = lane >> 2;          // 0..7
    const int cq = (lane & 3) * 2;     // 0,2,4,6
    #pragma unroll
    for (int mt = 0; mt < 2; ++mt) {
        #pragma unroll
        for (int nt = 0; nt < 8; ++nt) {
            const int row = m0 + warp_m * 32 + mt * 16 + rq;
            const int col = n0 + warp_n * 64 + nt * 8 + cq;
            const float* a4 = acc[mt][nt];
            if (mode == 2) {
                if (row < M)
                    *(float2*)(C + (size_t)row * ldc + col) =
                        make_float2(alpha * a4[0], alpha * a4[1]);
                if (row + 8 < M)
                    *(float2*)(C + (size_t)(row + 8) * ldc + col) =
                        make_float2(alpha * a4[2], alpha * a4[3]);
            } else {
                const float b0 = bias[col], b1 = bias[col + 1];
                if (mode == 0) {
                    if (row < M)
                        *(float2*)(C + (size_t)row * ldc + col) =
                            make_float2(eluf(a4[0] + b0), eluf(a4[1] + b1));
                    if (row + 8 < M)
                        *(float2*)(C + (size_t)(row + 8) * ldc + col) =
                            make_float2(eluf(a4[2] + b0), eluf(a4[3] + b1));
                } else {  // mode 1: transposed store out[n*ldc+m]
                    if (row < M) {
                        C[(size_t)col * ldc + row]       = eluf(a4[0] + b0);
                        C[(size_t)(col + 1) * ldc + row] = eluf(a4[1] + b1);
                    }
                    if (row + 8 < M) {
                        C[(size_t)col * ldc + row + 8]       = eluf(a4[2] + b0);
                        C[(size_t)(col + 1) * ldc + row + 8] = eluf(a4[3] + b1);
                    }
                }
            }
        }
    }
}

// =====================================================================
// transpose H [B, d, L] -> Ht [B, L, d]
// =====================================================================
__global__ void __launch_bounds__(256) transpose_hd(
    const float* __restrict__ H, float* __restrict__ Ht)
{
    __shared__ float tile[32][33];
    const int b  = blockIdx.z;
    const int l0 = blockIdx.x * 32, f0 = blockIdx.y * 32;
    const float* src = H + ((size_t)b * DD + f0) * LL + l0;
    for (int r = threadIdx.y; r < 32; r += 8)
        tile[r][threadIdx.x] = src[(size_t)r * LL + threadIdx.x];
    __syncthreads();
    float* dst = Ht + ((size_t)b * LL + l0) * DD + f0;
    for (int r = threadIdx.y; r < 32; r += 8)
        dst[(size_t)r * DD + threadIdx.x] = tile[threadIdx.x][r];
}

// =====================================================================
// Row softmax, fixed row length 4096, 256 threads
// =====================================================================
__global__ void __launch_bounds__(256) softmax4096(float* __restrict__ X)
{
    float* x = X + (size_t)blockIdx.x * 4096;
    const int tid = threadIdx.x;
    const int lane = tid & 31, wid = tid >> 5;
    __shared__ float red[32];

    float4 v[4];
    float mx = -1e30f;
    #pragma unroll
    for (int i = 0; i < 4; ++i) {
        v[i] = *(const float4*)&x[(i * 256 + tid) * 4];
        mx = fmaxf(mx, fmaxf(fmaxf(v[i].x, v[i].y), fmaxf(v[i].z, v[i].w)));
    }
    #pragma unroll
    for (int o = 16; o > 0; o >>= 1) mx = fmaxf(mx, __shfl_xor_sync(0xffffffffu, mx, o));
    if (lane == 0) red[wid] = mx;
    __syncthreads();
    if (wid == 0) {
        float m = (lane < 8) ? red[lane] : -1e30f;
        #pragma unroll
        for (int o = 4; o > 0; o >>= 1) m = fmaxf(m, __shfl_xor_sync(0xffffffffu, m, o));
        if (lane == 0) red[0] = m;
    }
    __syncthreads();
    mx = red[0];

    float sum = 0.0f;
    #pragma unroll
    for (int i = 0; i < 4; ++i) {
        v[i].x = __expf(v[i].x - mx);
        v[i].y = __expf(v[i].y - mx);
        v[i].z = __expf(v[i].z - mx);
        v[i].w = __expf(v[i].w - mx);
        sum += v[i].x + v[i].y + v[i].z + v[i].w;
    }
    #pragma unroll
    for (int o = 16; o > 0; o >>= 1) sum += __shfl_xor_sync(0xffffffffu, sum, o);
    if (lane == 0) red[16 + wid] = sum;
    __syncthreads();
    if (wid == 0) {
        float s = (lane < 8) ? red[16 + lane] : 0.0f;
        #pragma unroll
        for (int o = 4; o > 0; o >>= 1) s += __shfl_xor_sync(0xffffffffu, s, o);
        if (lane == 0) red[16] = s;
    }
    __syncthreads();
    const float inv = 1.0f / red[16];

    #pragma unroll
    for (int i = 0; i < 4; ++i) {
        v[i].x *= inv; v[i].y *= inv; v[i].z *= inv; v[i].w *= inv;
        *(float4*)&x[(i * 256 + tid) * 4] = v[i];
    }
}

// =====================================================================
// Q2b[b,n,:] = Q2[n,:] + C1[b, map[n], :]
// =====================================================================
__global__ void __launch_bounds__(128) q2b_kernel(
    const float* __restrict__ Q2, const int* __restrict__ cmap)
{
    const int n = blockIdx.x;
    const int b = blockIdx.y;
    const int c = cmap[n];
    const float4* q  = (const float4*)(Q2 + (size_t)n * DD);
    const float4* c1 = (const float4*)(g_C1 + ((size_t)b * NC1 + c) * DD);
    float4* out = (float4*)(g_Q2b + ((size_t)b * NLBL + n) * DD);
    const int i = threadIdx.x;
    float4 a = q[i], bb = c1[i];
    out[i] = make_float4(a.x + bb.x, a.y + bb.y, a.z + bb.z, a.w + bb.w);
}

// =====================================================================
// host
// =====================================================================
extern "C" void kernel_launch(void* const* d_in, const int* in_sizes, int n_in,
                              void* d_out, int out_size)
{
    const float* H    = (const float*)d_in[0];
    const float* Wk   = (const float*)d_in[1];
    const float* bk   = (const float*)d_in[2];
    const float* Wv   = (const float*)d_in[3];
    const float* bv   = (const float*)d_in[4];
    const float* Q1   = (const float*)d_in[5];
    const float* Q2   = (const float*)d_in[6];
    const int*   cmap = (const int*)d_in[7];

    float* C2 = (float*)d_out;                            // [B, Lbl, d]
    float* A2 = C2 + (size_t)BB * NLBL * DD;              // [B, Lbl, L]

    float *pHt, *pK, *pVt, *pE1, *pC1, *pQ2b;
    cudaGetSymbolAddress((void**)&pHt,  g_Ht);
    cudaGetSymbolAddress((void**)&pK,   g_K);
    cudaGetSymbolAddress((void**)&pVt,  g_Vt);
    cudaGetSymbolAddress((void**)&pE1,  g_E1);
    cudaGetSymbolAddress((void**)&pC1,  g_C1);
    cudaGetSymbolAddress((void**)&pQ2b, g_Q2b);

    cudaFuncSetAttribute(gemm_tc, cudaFuncAttributeMaxDynamicSharedMemorySize, SM_TOTAL);

    // 1) Ht = transpose(H)
    transpose_hd<<<dim3(LL / 32, DD / 32, BB), dim3(32, 8)>>>(H, pHt);

    // 2) K = elu(Ht Wk^T + bk)  -> [B, L, d]   (mode 0)
    gemm_tc<<<dim3(DD / 128, LL / 128, BB), 256, SM_TOTAL>>>(
        pHt, Wk, pK, bk, LL, DD, DD, DD, DD,
        (size_t)LL * DD, 0, (size_t)LL * DD, 1.0f, 0);

    // 3) Vt = elu(Ht Wv^T + bv)^T -> [B, d, L]  (mode 1)
    gemm_tc<<<dim3(DD / 128, LL / 128, BB), 256, SM_TOTAL>>>(
        pHt, Wv, pVt, bv, LL, DD, DD, DD, LL,
        (size_t)LL * DD, 0, (size_t)DD * LL, 1.0f, 1);

    // 4) E1 = Q1 K^T / SCALE -> [B, C1, L]  (mode 2)
    gemm_tc<<<dim3(LL / 128, (NC1 + 127) / 128, BB), 256, SM_TOTAL>>>(
        Q1, pK, pE1, bk, NC1, DD, DD, DD, LL,
        0, (size_t)LL * DD, (size_t)NC1 * LL, SCALE_INV, 2);

    // 5) softmax
    softmax4096<<<BB * NC1, 256>>>(pE1);

    // 6) C1 = A1 Vt^T -> [B, C1, d]  (mode 2, alpha=1)
    gemm_tc<<<dim3(DD / 128, (NC1 + 127) / 128, BB), 256, SM_TOTAL>>>(
        pE1, pVt, pC1, bk, NC1, LL, LL, LL, DD,
        (size_t)NC1 * LL, (size_t)DD * LL, (size_t)NC1 * DD, 1.0f, 2);

    // 7) Q2b = Q2 + C1[:, map, :]
    q2b_kernel<<<dim3(NLBL, BB), 128>>>(Q2, cmap);

    // 8) E2 = Q2b K^T / SCALE -> A2 region  (mode 2)
    gemm_tc<<<dim3(LL / 128, (NLBL + 127) / 128, BB), 256, SM_TOTAL>>>(
        pQ2b, pK, A2, bk, NLBL, DD, DD, DD, LL,
        (size_t)NLBL * DD, (size_t)LL * DD, (size_t)NLBL * LL, SCALE_INV, 2);

    // 9) softmax (in place in output)
    softmax4096<<<BB * NLBL, 256>>>(A2);

    // 10) C2 = A2 Vt^T -> [B, Lbl, d]  (mode 2, alpha=1)
    gemm_tc<<<dim3(DD / 128, (NLBL + 127) / 128, BB), 256, SM_TOTAL>>>(
        A2, pVt, C2, bk, NLBL, LL, LL, LL, DD,
        (size_t)NLBL * LL, (size_t)DD * LL, (size_t)NLBL * DD, 1.0f, 2);
}

// round 5
// speedup vs baseline: 1.8335x; 1.1606x over previous
#include <cuda_runtime.h>
#include <math.h>
#include <stdint.h>

// Problem dims (fixed)
#define BB   4
#define DD   512
#define LL   4096
#define NC1  1168
#define NLBL 8929

#define SCALE_INV 0.044194173824159216f  // 1/sqrt(512)

#define KC 32

// smem: double-buffered A (16KB x2), Bhi (16KB x2), Blo (16KB x2) = 96KB
#define SA0  0
#define SA1  16384
#define SBH0 32768
#define SBH1 49152
#define SBL0 65536
#define SBL1 81920
#define SM_TOTAL 98304

// ---------------- device scratch ----------------
__device__ float g_Ht  [(size_t)BB * LL * DD];     // [B, L, d]
__device__ float g_Khi [(size_t)BB * LL * DD];     // [B, L, d] tf32-hi
__device__ float g_Klo [(size_t)BB * LL * DD];     // [B, L, d] tf32-lo
__device__ float g_Vthi[(size_t)BB * DD * LL];     // [B, d, L] tf32-hi
__device__ float g_Vtlo[(size_t)BB * DD * LL];     // [B, d, L] tf32-lo
__device__ float g_E1  [(size_t)BB * NC1 * LL];    // [B, C1, L]
__device__ float g_C1  [(size_t)BB * NC1 * DD];    // [B, C1, d]
__device__ float g_Q2b [(size_t)BB * NLBL * DD];   // [B, Lbl, d]
__device__ float g_Wkhi[(size_t)DD * DD];
__device__ float g_Wklo[(size_t)DD * DD];
__device__ float g_Wvhi[(size_t)DD * DD];
__device__ float g_Wvlo[(size_t)DD * DD];

// ---------------- helpers ----------------
__device__ __forceinline__ uint32_t smem_u32(const void* p) {
    uint32_t a;
    asm("{ .reg .u64 t; cvta.to.shared.u64 t, %1; cvt.u32.u64 %0, t; }" : "=r"(a) : "l"(p));
    return a;
}
__device__ __forceinline__ void cp16(uint32_t dst, const float* src, bool pred) {
    int sz = pred ? 16 : 0;
    asm volatile("cp.async.cg.shared.global [%0], [%1], 16, %2;"
                 :: "r"(dst), "l"(src), "r"(sz));
}
__device__ __forceinline__ void cp_commit() {
    asm volatile("cp.async.commit_group;" ::: "memory");
}
__device__ __forceinline__ void ldsm4(uint32_t* r, uint32_t addr) {
    asm volatile("ldmatrix.sync.aligned.m8n8.x4.shared.b16 {%0,%1,%2,%3}, [%4];"
                 : "=r"(r[0]), "=r"(r[1]), "=r"(r[2]), "=r"(r[3]) : "r"(addr));
}
__device__ __forceinline__ void mma_tf32(float* d, const uint32_t* a, const uint32_t* b) {
    asm volatile(
        "mma.sync.aligned.m16n8k8.row.col.f32.tf32.tf32.f32 "
        "{%0,%1,%2,%3}, {%4,%5,%6,%7}, {%8,%9}, {%0,%1,%2,%3};"
        : "+f"(d[0]), "+f"(d[1]), "+f"(d[2]), "+f"(d[3])
        : "r"(a[0]), "r"(a[1]), "r"(a[2]), "r"(a[3]), "r"(b[0]), "r"(b[1]));
}
__device__ __forceinline__ void split_tf32(uint32_t x, uint32_t& hi, uint32_t& lo) {
    float xf = __uint_as_float(x);
    asm("cvt.rna.tf32.f32 %0, %1;" : "=r"(hi) : "f"(xf));
    float rf = xf - __uint_as_float(hi);
    asm("cvt.rna.tf32.f32 %0, %1;" : "=r"(lo) : "f"(rf));
}
__device__ __forceinline__ void fsplit(float x, float& hi, float& lo) {
    uint32_t h, l;
    asm("cvt.rna.tf32.f32 %0, %1;" : "=r"(h) : "f"(x));
    hi = __uint_as_float(h);
    float r = x - hi;
    asm("cvt.rna.tf32.f32 %0, %1;" : "=r"(l) : "f"(r));
    lo = __uint_as_float(l);
}
__device__ __forceinline__ float eluf(float x) { return x > 0.0f ? x : expm1f(x); }

// =====================================================================
// 3xTF32 mma.sync NT GEMM: D[m,n] = sum_k A[m,k]*B[n,k]
// A: [M, K] fp32 (split in registers). Bhi/Blo: [N, K] pre-split tf32.
// mode 0: split(elu(acc+bias[n])) -> Chi[m*ldc+n], Clo[m*ldc+n]
// mode 1: split(elu(acc+bias[n])) -> Chi[n*ldc+m], Clo[n*ldc+m]  (transposed)
// mode 2: C[m*ldc+n] = alpha * acc
// N, K multiples of 128 / 32; M may be ragged.
// =====================================================================
__global__ void __launch_bounds__(256, 2) gemm_tc(
    const float* __restrict__ Ab,
    const float* __restrict__ Bhib, const float* __restrict__ Blob,
    float* __restrict__ Cb, float* __restrict__ Clob,
    const float* __restrict__ bias,
    int M, int K, int lda, int ldb, int ldc,
    size_t sA, size_t sB, size_t sC, float alpha, int mode)
{
    extern __shared__ char smem[];
    const uint32_t sbase = smem_u32(smem);

    const int tid  = threadIdx.x;
    const int wid  = tid >> 5;
    const int lane = tid & 31;
    const int g    = lane >> 3;
    const int r    = lane & 7;
    const int warp_m = wid & 3;
    const int warp_n = wid >> 2;

    const float* A   = Ab   + (size_t)blockIdx.z * sA;
    const float* Bhi = Bhib + (size_t)blockIdx.z * sB;
    const float* Blo = Blob + (size_t)blockIdx.z * sB;
    float*       C   = Cb   + (size_t)blockIdx.z * sC;
    float*       Clo = Clob + (size_t)blockIdx.z * sC;
    const int m0 = blockIdx.y * 128;
    const int n0 = blockIdx.x * 128;

    const uint32_t sw = (uint32_t)r * 16;
    uint32_t aRow[2], bRow[4];
    #pragma unroll
    for (int mt = 0; mt < 2; ++mt)
        aRow[mt] = (uint32_t)(warp_m * 32 + mt * 16 + (g & 1) * 8 + r) * 128;
    const uint32_t akb = (uint32_t)(g >> 1) * 16;
    #pragma unroll
    for (int p = 0; p < 4; ++p)
        bRow[p] = (uint32_t)(warp_n * 64 + (p * 2 + (g >> 1)) * 8 + r) * 128;
    const uint32_t bkb = (uint32_t)(g & 1) * 16;

    const int srow = tid >> 3;
    const int sc4  = tid & 7;
    const uint32_t sdst_off = (uint32_t)(sc4 * 16);

    float acc[2][8][4];
    #pragma unroll
    for (int mt = 0; mt < 2; ++mt)
        #pragma unroll
        for (int nt = 0; nt < 8; ++nt)
            #pragma unroll
            for (int c = 0; c < 4; ++c) acc[mt][nt][c] = 0.0f;

    const int nc = K >> 5;

    // ---- stage chunk 0 ----
    {
        const uint32_t ab  = sbase + SA0;
        const uint32_t bhb = sbase + SBH0;
        const uint32_t blb = sbase + SBL0;
        #pragma unroll
        for (int q = 0; q < 4; ++q) {
            int row = srow + q * 32;
            int m = m0 + row;
            const float* src = A + (size_t)(m < M ? m : 0) * lda + sc4 * 4;
            cp16(ab + (uint32_t)row * 128 + (sdst_off ^ ((row & 7) * 16)), src, m < M);
        }
        #pragma unroll
        for (int q = 0; q < 4; ++q) {
            int row = srow + q * 32;
            size_t boff = (size_t)(n0 + row) * ldb + sc4 * 4;
            uint32_t d = (uint32_t)row * 128 + (sdst_off ^ ((row & 7) * 16));
            cp16(bhb + d, Bhi + boff, true);
            cp16(blb + d, Blo + boff, true);
        }
        cp_commit();
    }

    for (int i = 0; i < nc; ++i) {
        const int b = i & 1;
        if (i + 1 < nc) {
            const int k0 = (i + 1) * KC;
            const uint32_t ab  = sbase + (b ? SA0  : SA1);
            const uint32_t bhb = sbase + (b ? SBH0 : SBH1);
            const uint32_t blb = sbase + (b ? SBL0 : SBL1);
            #pragma unroll
            for (int q = 0; q < 4; ++q) {
                int row = srow + q * 32;
                int m = m0 + row;
                const float* src = A + (size_t)(m < M ? m : 0) * lda + k0 + sc4 * 4;
                cp16(ab + (uint32_t)row * 128 + (sdst_off ^ ((row & 7) * 16)), src, m < M);
            }
            #pragma unroll
            for (int q = 0; q < 4; ++q) {
                int row = srow + q * 32;
                size_t boff = (size_t)(n0 + row) * ldb + k0 + sc4 * 4;
                uint32_t d = (uint32_t)row * 128 + (sdst_off ^ ((row & 7) * 16));
                cp16(bhb + d, Bhi + boff, true);
                cp16(blb + d, Blo + boff, true);
            }
            cp_commit();
            asm volatile("cp.async.wait_group 1;" ::: "memory");
        } else {
            asm volatile("cp.async.wait_group 0;" ::: "memory");
        }
        __syncthreads();

        const uint32_t abase  = sbase + (b ? SA1  : SA0);
        const uint32_t bhbase = sbase + (b ? SBH1 : SBH0);
        const uint32_t blbase = sbase + (b ? SBL1 : SBL0);
        #pragma unroll
        for (int ks = 0; ks < 4; ++ks) {
            const uint32_t kb = (uint32_t)ks * 32;
            uint32_t araw[2][4], ah[2][4], al[2][4];
            ldsm4(araw[0], abase + aRow[0] + ((kb + akb) ^ sw));
            ldsm4(araw[1], abase + aRow[1] + ((kb + akb) ^ sw));
            #pragma unroll
            for (int mt = 0; mt < 2; ++mt)
                #pragma unroll
                for (int e = 0; e < 4; ++e)
                    split_tf32(araw[mt][e], ah[mt][e], al[mt][e]);

            #pragma unroll
            for (int p = 0; p < 4; ++p) {
                uint32_t bh[4], bl[4];
                const uint32_t bo = bRow[p] + ((kb + bkb) ^ sw);
                ldsm4(bh, bhbase + bo);
                ldsm4(bl, blbase + bo);
                #pragma unroll
                for (int h = 0; h < 2; ++h) {
                    const int nt = p * 2 + h;
                    #pragma unroll
                    for (int mt = 0; mt < 2; ++mt) {
                        mma_tf32(acc[mt][nt], ah[mt], &bh[h * 2]);   // hi*hi
                        mma_tf32(acc[mt][nt], ah[mt], &bl[h * 2]);   // hi*lo
                        mma_tf32(acc[mt][nt], al[mt], &bh[h * 2]);   // lo*hi
                    }
                }
            }
        }
        __syncthreads();
    }

    // ---- epilogue ----
    const int rq = lane >> 2;
    const int cq = (lane & 3) * 2;
    #pragma unroll
    for (int mt = 0; mt < 2; ++mt) {
        #pragma unroll
        for (int nt = 0; nt < 8; ++nt) {
            const int row = m0 + warp_m * 32 + mt * 16 + rq;
            const int col = n0 + warp_n * 64 + nt * 8 + cq;
            const float* a4 = acc[mt][nt];
            if (mode == 2) {
                if (row < M)
                    *(float2*)(C + (size_t)row * ldc + col) =
                        make_float2(alpha * a4[0], alpha * a4[1]);
                if (row + 8 < M)
                    *(float2*)(C + (size_t)(row + 8) * ldc + col) =
                        make_float2(alpha * a4[2], alpha * a4[3]);
            } else {
                const float b0 = bias[col], b1 = bias[col + 1];
                float h0, l0, h1, l1, h2, l2, h3, l3;
                fsplit(eluf(a4[0] + b0), h0, l0);
                fsplit(eluf(a4[1] + b1), h1, l1);
                fsplit(eluf(a4[2] + b0), h2, l2);
                fsplit(eluf(a4[3] + b1), h3, l3);
                if (mode == 0) {
                    if (row < M) {
                        *(float2*)(C   + (size_t)row * ldc + col) = make_float2(h0, h1);
                        *(float2*)(Clo + (size_t)row * ldc + col) = make_float2(l0, l1);
                    }
                    if (row + 8 < M) {
                        *(float2*)(C   + (size_t)(row + 8) * ldc + col) = make_float2(h2, h3);
                        *(float2*)(Clo + (size_t)(row + 8) * ldc + col) = make_float2(l2, l3);
                    }
                } else {  // mode 1: transposed store
                    if (row < M) {
                        C  [(size_t)col * ldc + row]       = h0;
                        Clo[(size_t)col * ldc + row]       = l0;
                        C  [(size_t)(col + 1) * ldc + row] = h1;
                        Clo[(size_t)(col + 1) * ldc + row] = l1;
                    }
                    if (row + 8 < M) {
                        C  [(size_t)col * ldc + row + 8]       = h2;
                        Clo[(size_t)col * ldc + row + 8]       = l2;
                        C  [(size_t)(col + 1) * ldc + row + 8] = h3;
                        Clo[(size_t)(col + 1) * ldc + row + 8] = l3;
                    }
                }
            }
        }
    }
}

// =====================================================================
// split an fp32 array into tf32 hi/lo
// =====================================================================
__global__ void __launch_bounds__(256) split_arr(
    const float* __restrict__ src, float* __restrict__ hi,
    float* __restrict__ lo, int n)
{
    int i = blockIdx.x * 256 + threadIdx.x;
    if (i < n) {
        float h, l;
        fsplit(src[i], h, l);
        hi[i] = h; lo[i] = l;
    }
}

// =====================================================================
// transpose H [B, d, L] -> Ht [B, L, d]
// =====================================================================
__global__ void __launch_bounds__(256) transpose_hd(
    const float* __restrict__ H, float* __restrict__ Ht)
{
    __shared__ float tile[32][33];
    const int b  = blockIdx.z;
    const int l0 = blockIdx.x * 32, f0 = blockIdx.y * 32;
    const float* src = H + ((size_t)b * DD + f0) * LL + l0;
    for (int r = threadIdx.y; r < 32; r += 8)
        tile[r][threadIdx.x] = src[(size_t)r * LL + threadIdx.x];
    __syncthreads();
    float* dst = Ht + ((size_t)b * LL + l0) * DD + f0;
    for (int r = threadIdx.y; r < 32; r += 8)
        dst[(size_t)r * DD + threadIdx.x] = tile[threadIdx.x][r];
}

// =====================================================================
// Row softmax, fixed row length 4096, 256 threads
// =====================================================================
__global__ void __launch_bounds__(256) softmax4096(float* __restrict__ X)
{
    float* x = X + (size_t)blockIdx.x * 4096;
    const int tid = threadIdx.x;
    const int lane = tid & 31, wid = tid >> 5;
    __shared__ float red[32];

    float4 v[4];
    float mx = -1e30f;
    #pragma unroll
    for (int i = 0; i < 4; ++i) {
        v[i] = *(const float4*)&x[(i * 256 + tid) * 4];
        mx = fmaxf(mx, fmaxf(fmaxf(v[i].x, v[i].y), fmaxf(v[i].z, v[i].w)));
    }
    #pragma unroll
    for (int o = 16; o > 0; o >>= 1) mx = fmaxf(mx, __shfl_xor_sync(0xffffffffu, mx, o));
    if (lane == 0) red[wid] = mx;
    __syncthreads();
    if (wid == 0) {
        float m = (lane < 8) ? red[lane] : -1e30f;
        #pragma unroll
        for (int o = 4; o > 0; o >>= 1) m = fmaxf(m, __shfl_xor_sync(0xffffffffu, m, o));
        if (lane == 0) red[0] = m;
    }
    __syncthreads();
    mx = red[0];

    float sum = 0.0f;
    #pragma unroll
    for (int i = 0; i < 4; ++i) {
        v[i].x = __expf(v[i].x - mx);
        v[i].y = __expf(v[i].y - mx);
        v[i].z = __expf(v[i].z - mx);
        v[i].w = __expf(v[i].w - mx);
        sum += v[i].x + v[i].y + v[i].z + v[i].w;
    }
    #pragma unroll
    for (int o = 16; o > 0; o >>= 1) sum += __shfl_xor_sync(0xffffffffu, sum, o);
    if (lane == 0) red[16 + wid] = sum;
    __syncthreads();
    if (wid == 0) {
        float s = (lane < 8) ? red[16 + lane] : 0.0f;
        #pragma unroll
        for (int o = 4; o > 0; o >>= 1) s += __shfl_xor_sync(0xffffffffu, s, o);
        if (lane == 0) red[16] = s;
    }
    __syncthreads();
    const float inv = 1.0f / red[16];

    #pragma unroll
    for (int i = 0; i < 4; ++i) {
        v[i].x *= inv; v[i].y *= inv; v[i].z *= inv; v[i].w *= inv;
        *(float4*)&x[(i * 256 + tid) * 4] = v[i];
    }
}

// =====================================================================
// Q2b[b,n,:] = Q2[n,:] + C1[b, map[n], :]
// =====================================================================
__global__ void __launch_bounds__(128) q2b_kernel(
    const float* __restrict__ Q2, const int* __restrict__ cmap)
{
    const int n = blockIdx.x;
    const int b = blockIdx.y;
    const int c = cmap[n];
    const float4* q  = (const float4*)(Q2 + (size_t)n * DD);
    const float4* c1 = (const float4*)(g_C1 + ((size_t)b * NC1 + c) * DD);
    float4* out = (float4*)(g_Q2b + ((size_t)b * NLBL + n) * DD);
    const int i = threadIdx.x;
    float4 a = q[i], bb = c1[i];
    out[i] = make_float4(a.x + bb.x, a.y + bb.y, a.z + bb.z, a.w + bb.w);
}

// =====================================================================
// host
// =====================================================================
extern "C" void kernel_launch(void* const* d_in, const int* in_sizes, int n_in,
                              void* d_out, int out_size)
{
    const float* H    = (const float*)d_in[0];
    const float* Wk   = (const float*)d_in[1];
    const float* bk   = (const float*)d_in[2];
    const float* Wv   = (const float*)d_in[3];
    const float* bv   = (const float*)d_in[4];
    const float* Q1   = (const float*)d_in[5];
    const float* Q2   = (const float*)d_in[6];
    const int*   cmap = (const int*)d_in[7];

    float* C2 = (float*)d_out;                            // [B, Lbl, d]
    float* A2 = C2 + (size_t)BB * NLBL * DD;              // [B, Lbl, L]

    float *pHt, *pKhi, *pKlo, *pVthi, *pVtlo, *pE1, *pC1, *pQ2b;
    float *pWkhi, *pWklo, *pWvhi, *pWvlo;
    cudaGetSymbolAddress((void**)&pHt,   g_Ht);
    cudaGetSymbolAddress((void**)&pKhi,  g_Khi);
    cudaGetSymbolAddress((void**)&pKlo,  g_Klo);
    cudaGetSymbolAddress((void**)&pVthi, g_Vthi);
    cudaGetSymbolAddress((void**)&pVtlo, g_Vtlo);
    cudaGetSymbolAddress((void**)&pE1,   g_E1);
    cudaGetSymbolAddress((void**)&pC1,   g_C1);
    cudaGetSymbolAddress((void**)&pQ2b,  g_Q2b);
    cudaGetSymbolAddress((void**)&pWkhi, g_Wkhi);
    cudaGetSymbolAddress((void**)&pWklo, g_Wklo);
    cudaGetSymbolAddress((void**)&pWvhi, g_Wvhi);
    cudaGetSymbolAddress((void**)&pWvlo, g_Wvlo);

    cudaFuncSetAttribute(gemm_tc, cudaFuncAttributeMaxDynamicSharedMemorySize, SM_TOTAL);

    // 0) split the weights
    split_arr<<<(DD * DD + 255) / 256, 256>>>(Wk, pWkhi, pWklo, DD * DD);
    split_arr<<<(DD * DD + 255) / 256, 256>>>(Wv, pWvhi, pWvlo, DD * DD);

    // 1) Ht = transpose(H)
    transpose_hd<<<dim3(LL / 32, DD / 32, BB), dim3(32, 8)>>>(H, pHt);

    // 2) Khi/Klo = split(elu(Ht Wk^T + bk))  [B,L,d]  (mode 0)
    gemm_tc<<<dim3(DD / 128, LL / 128, BB), 256, SM_TOTAL>>>(
        pHt, pWkhi, pWklo, pKhi, pKlo, bk, LL, DD, DD, DD, DD,
        (size_t)LL * DD, 0, (size_t)LL * DD, 1.0f, 0);

    // 3) Vthi/Vtlo = split(elu(Ht Wv^T + bv))^T  [B,d,L]  (mode 1)
    gemm_tc<<<dim3(DD / 128, LL / 128, BB), 256, SM_TOTAL>>>(
        pHt, pWvhi, pWvlo, pVthi, pVtlo, bv, LL, DD, DD, DD, LL,
        (size_t)LL * DD, 0, (size_t)DD * LL, 1.0f, 1);

    // 4) E1 = Q1 K^T / SCALE  [B,C1,L]  (mode 2)
    gemm_tc<<<dim3(LL / 128, (NC1 + 127) / 128, BB), 256, SM_TOTAL>>>(
        Q1, pKhi, pKlo, pE1, pE1, bk, NC1, DD, DD, DD, LL,
        0, (size_t)LL * DD, (size_t)NC1 * LL, SCALE_INV, 2);

    // 5) softmax
    softmax4096<<<BB * NC1, 256>>>(pE1);

    // 6) C1 = A1 Vt^T  [B,C1,d]  (mode 2)
    gemm_tc<<<dim3(DD / 128, (NC1 + 127) / 128, BB), 256, SM_TOTAL>>>(
        pE1, pVthi, pVtlo, pC1, pC1, bk, NC1, LL, LL, LL, DD,
        (size_t)NC1 * LL, (size_t)DD * LL, (size_t)NC1 * DD, 1.0f, 2);

    // 7) Q2b = Q2 + C1[:, map, :]
    q2b_kernel<<<dim3(NLBL, BB), 128>>>(Q2, cmap);

    // 8) E2 = Q2b K^T / SCALE -> A2 region  (mode 2)
    gemm_tc<<<dim3(LL / 128, (NLBL + 127) / 128, BB), 256, SM_TOTAL>>>(
        pQ2b, pKhi, pKlo, A2, A2, bk, NLBL, DD, DD, DD, LL,
        (size_t)NLBL * DD, (size_t)LL * DD, (size_t)NLBL * LL, SCALE_INV, 2);

    // 9) softmax (in place in output)
    softmax4096<<<BB * NLBL, 256>>>(A2);

    // 10) C2 = A2 Vt^T  [B,Lbl,d]  (mode 2)
    gemm_tc<<<dim3(DD / 128, (NLBL + 127) / 128, BB), 256, SM_TOTAL>>>(
        A2, pVthi, pVtlo, C2, C2, bk, NLBL, LL, LL, LL, DD,
        (size_t)NLBL * LL, (size_t)DD * LL, (size_t)NLBL * DD, 1.0f, 2);
}

// round 6
// speedup vs baseline: 3.2665x; 1.7816x over previous
#include <cuda_runtime.h>
#include <cuda_bf16.h>
#include <math.h>
#include <stdint.h>

// Problem dims (fixed)
#define BB   4
#define DD   512
#define LL   4096
#define NC1  1168
#define NLBL 8929

#define SCALE_INV 0.044194173824159216f  // 1/sqrt(512)

#define KC 32   // K elements per chunk (bf16), 64B rows

// smem: double-buffered Ahi/Alo/Bhi/Blo, each 128x32 bf16 = 8KB
#define S_AH0 0
#define S_AH1 8192
#define S_AL0 16384
#define S_AL1 24576
#define S_BH0 32768
#define S_BH1 40960
#define S_BL0 49152
#define S_BL1 57344
#define SM_TOTAL 65536

typedef __nv_bfloat16 bf16;

// ---------------- device scratch ----------------
__device__ bf16  g_Hthi [(size_t)BB * LL * DD];
__device__ bf16  g_Htlo [(size_t)BB * LL * DD];
__device__ bf16  g_Khi  [(size_t)BB * LL * DD];     // [B, L, d]
__device__ bf16  g_Klo  [(size_t)BB * LL * DD];
__device__ bf16  g_Vthi [(size_t)BB * DD * LL];     // [B, d, L]
__device__ bf16  g_Vtlo [(size_t)BB * DD * LL];
__device__ float g_E1   [(size_t)BB * NC1 * LL];    // [B, C1, L]
__device__ bf16  g_A1hi [(size_t)BB * NC1 * LL];
__device__ bf16  g_A1lo [(size_t)BB * NC1 * LL];
__device__ float g_C1   [(size_t)BB * NC1 * DD];    // [B, C1, d]
__device__ bf16  g_Q2bhi[(size_t)BB * NLBL * DD];
__device__ bf16  g_Q2blo[(size_t)BB * NLBL * DD];
__device__ bf16  g_A2hi [(size_t)BB * NLBL * LL];
__device__ bf16  g_A2lo [(size_t)BB * NLBL * LL];
__device__ bf16  g_Wkhi [(size_t)DD * DD];
__device__ bf16  g_Wklo [(size_t)DD * DD];
__device__ bf16  g_Wvhi [(size_t)DD * DD];
__device__ bf16  g_Wvlo [(size_t)DD * DD];
__device__ bf16  g_Q1hi [(size_t)NC1 * DD];
__device__ bf16  g_Q1lo [(size_t)NC1 * DD];

// ---------------- helpers ----------------
__device__ __forceinline__ uint32_t smem_u32(const void* p) {
    uint32_t a;
    asm("{ .reg .u64 t; cvta.to.shared.u64 t, %1; cvt.u32.u64 %0, t; }" : "=r"(a) : "l"(p));
    return a;
}
__device__ __forceinline__ void cp16(uint32_t dst, const void* src, bool pred) {
    int sz = pred ? 16 : 0;
    asm volatile("cp.async.cg.shared.global [%0], [%1], 16, %2;"
                 :: "r"(dst), "l"(src), "r"(sz));
}
__device__ __forceinline__ void cp_commit() {
    asm volatile("cp.async.commit_group;" ::: "memory");
}
__device__ __forceinline__ void ldsm4(uint32_t* r, uint32_t addr) {
    asm volatile("ldmatrix.sync.aligned.m8n8.x4.shared.b16 {%0,%1,%2,%3}, [%4];"
                 : "=r"(r[0]), "=r"(r[1]), "=r"(r[2]), "=r"(r[3]) : "r"(addr));
}
__device__ __forceinline__ void mma_bf16(float* d, const uint32_t* a, const uint32_t* b) {
    asm volatile(
        "mma.sync.aligned.m16n8k16.row.col.f32.bf16.bf16.f32 "
        "{%0,%1,%2,%3}, {%4,%5,%6,%7}, {%8,%9}, {%0,%1,%2,%3};"
        : "+f"(d[0]), "+f"(d[1]), "+f"(d[2]), "+f"(d[3])
        : "r"(a[0]), "r"(a[1]), "r"(a[2]), "r"(a[3]), "r"(b[0]), "r"(b[1]));
}
__device__ __forceinline__ void bsplit(float x, bf16& h, bf16& l) {
    h = __float2bfloat16_rn(x);
    l = __float2bfloat16_rn(x - __bfloat162float(h));
}
__device__ __forceinline__ float eluf(float x) { return x > 0.0f ? x : expm1f(x); }

// =====================================================================
// 3xBF16 mma.sync NT GEMM: D[m,n] = sum_k A[m,k]*B[n,k]
// A, B pre-split bf16 hi/lo, K-major.
// mode 0: split(elu(acc+bias[n])) -> Chi/Clo[m*ldc+n]  (bf16)
// mode 1: split(elu(acc+bias[n])) -> Chi/Clo[n*ldc+m]  (bf16, transposed)
// mode 2: Cf[m*ldc+n] = alpha * acc                     (fp32)
// N, K multiples of 128 / 32; M may be ragged.
// =====================================================================
__global__ void __launch_bounds__(256, 2) gemm_tc(
    const bf16* __restrict__ Ahi, const bf16* __restrict__ Alo,
    const bf16* __restrict__ Bhi, const bf16* __restrict__ Blo,
    float* __restrict__ Cf, bf16* __restrict__ Chi, bf16* __restrict__ Clo,
    const float* __restrict__ bias,
    int M, int K, int lda, int ldb, int ldc,
    size_t sA, size_t sB, size_t sC, float alpha, int mode)
{
    extern __shared__ char smem[];
    const uint32_t sbase = smem_u32(smem);

    const int tid  = threadIdx.x;
    const int wid  = tid >> 5;
    const int lane = tid & 31;
    const int g    = lane >> 3;
    const int r    = lane & 7;
    const int warp_m = wid & 3;
    const int warp_n = wid >> 2;

    const bf16* Ah = Ahi + (size_t)blockIdx.z * sA;
    const bf16* Al = Alo + (size_t)blockIdx.z * sA;
    const bf16* Bh = Bhi + (size_t)blockIdx.z * sB;
    const bf16* Bl = Blo + (size_t)blockIdx.z * sB;
    const int m0 = blockIdx.y * 128;
    const int n0 = blockIdx.x * 128;

    // ldmatrix offsets within a tile (rows of 64B, swizzle: quad ^= (row>>1)&3)
    uint32_t aoff[2], aswz[2], boff[4], bswz[4];
    #pragma unroll
    for (int mt = 0; mt < 2; ++mt) {
        int row = warp_m * 32 + mt * 16 + (g & 1) * 8 + r;
        aoff[mt] = (uint32_t)row * 64;
        aswz[mt] = (uint32_t)((row >> 1) & 3);
    }
    const uint32_t aq = (uint32_t)(g >> 1);
    #pragma unroll
    for (int p = 0; p < 4; ++p) {
        int row = warp_n * 64 + p * 16 + (g >> 1) * 8 + r;
        boff[p] = (uint32_t)row * 64;
        bswz[p] = (uint32_t)((row >> 1) & 3);
    }
    const uint32_t bq = (uint32_t)(g & 1);

    // cp.async staging: 512 lines of 16B per tile, 2 per thread
    const int sr0 = tid >> 2;          // rows sr0 and sr0+64
    const int sq  = tid & 3;           // quad (8 bf16)

    float acc[2][8][4];
    #pragma unroll
    for (int mt = 0; mt < 2; ++mt)
        #pragma unroll
        for (int nt = 0; nt < 8; ++nt)
            #pragma unroll
            for (int c = 0; c < 4; ++c) acc[mt][nt][c] = 0.0f;

    const int nc = K >> 5;

    // stage helper (emitted twice: prologue + loop)
#define STAGE(AHB, ALB, BHB, BLB, K0)                                            \
    {                                                                            \
        _Pragma("unroll")                                                        \
        for (int q = 0; q < 2; ++q) {                                            \
            int row = sr0 + q * 64;                                              \
            uint32_t d = (uint32_t)row * 64 + ((sq ^ ((row >> 1) & 3)) << 4);    \
            int m = m0 + row;                                                    \
            size_t ao = (size_t)(m < M ? m : 0) * lda + (K0) + sq * 8;           \
            cp16((AHB) + d, Ah + ao, m < M);                                     \
            cp16((ALB) + d, Al + ao, m < M);                                     \
            size_t bo = (size_t)(n0 + row) * ldb + (K0) + sq * 8;                \
            cp16((BHB) + d, Bh + bo, true);                                      \
            cp16((BLB) + d, Bl + bo, true);                                      \
        }                                                                        \
        cp_commit();                                                             \
    }

    STAGE(sbase + S_AH0, sbase + S_AL0, sbase + S_BH0, sbase + S_BL0, 0)

    for (int i = 0; i < nc; ++i) {
        const int b = i & 1;
        if (i + 1 < nc) {
            const int k0 = (i + 1) * KC;
            if (b) { STAGE(sbase + S_AH0, sbase + S_AL0, sbase + S_BH0, sbase + S_BL0, k0) }
            else   { STAGE(sbase + S_AH1, sbase + S_AL1, sbase + S_BH1, sbase + S_BL1, k0) }
            asm volatile("cp.async.wait_group 1;" ::: "memory");
        } else {
            asm volatile("cp.async.wait_group 0;" ::: "memory");
        }
        __syncthreads();

        const uint32_t ahb = sbase + (b ? S_AH1 : S_AH0);
        const uint32_t alb = sbase + (b ? S_AL1 : S_AL0);
        const uint32_t bhb = sbase + (b ? S_BH1 : S_BH0);
        const uint32_t blb = sbase + (b ? S_BL1 : S_BL0);

        #pragma unroll
        for (int ks = 0; ks < 2; ++ks) {
            const uint32_t qa = (uint32_t)(ks * 2) + aq;
            const uint32_t qb = (uint32_t)(ks * 2) + bq;
            uint32_t ah[2][4], al[2][4];
            #pragma unroll
            for (int mt = 0; mt < 2; ++mt) {
                const uint32_t o = aoff[mt] + ((qa ^ aswz[mt]) << 4);
                ldsm4(ah[mt], ahb + o);
                ldsm4(al[mt], alb + o);
            }
            #pragma unroll
            for (int p = 0; p < 4; ++p) {
                uint32_t bhf[4], blf[4];
                const uint32_t o = boff[p] + ((qb ^ bswz[p]) << 4);
                ldsm4(bhf, bhb + o);
                ldsm4(blf, blb + o);
                #pragma unroll
                for (int h2 = 0; h2 < 2; ++h2) {
                    const int nt = p * 2 + h2;
                    #pragma unroll
                    for (int mt = 0; mt < 2; ++mt) {
                        mma_bf16(acc[mt][nt], ah[mt], &bhf[h2 * 2]);  // hi*hi
                        mma_bf16(acc[mt][nt], ah[mt], &blf[h2 * 2]);  // hi*lo
                        mma_bf16(acc[mt][nt], al[mt], &bhf[h2 * 2]);  // lo*hi
                    }
                }
            }
        }
        __syncthreads();
    }
#undef STAGE

    // ---- epilogue ----
    const int rq = lane >> 2;
    const int cq = (lane & 3) * 2;
    float*       C   = Cf  ? Cf  + (size_t)blockIdx.z * sC : (float*)0;
    bf16*        CH  = Chi ? Chi + (size_t)blockIdx.z * sC : (bf16*)0;
    bf16*        CL  = Clo ? Clo + (size_t)blockIdx.z * sC : (bf16*)0;
    #pragma unroll
    for (int mt = 0; mt < 2; ++mt) {
        #pragma unroll
        for (int nt = 0; nt < 8; ++nt) {
            const int row = m0 + warp_m * 32 + mt * 16 + rq;
            const int col = n0 + warp_n * 64 + nt * 8 + cq;
            const float* a4 = acc[mt][nt];
            if (mode == 2) {
                if (row < M)
                    *(float2*)(C + (size_t)row * ldc + col) =
                        make_float2(alpha * a4[0], alpha * a4[1]);
                if (row + 8 < M)
                    *(float2*)(C + (size_t)(row + 8) * ldc + col) =
                        make_float2(alpha * a4[2], alpha * a4[3]);
            } else {
                const float b0 = bias[col], b1 = bias[col + 1];
                bf16 h0, l0, h1, l1, h2, l2, h3, l3;
                bsplit(eluf(a4[0] + b0), h0, l0);
                bsplit(eluf(a4[1] + b1), h1, l1);
                bsplit(eluf(a4[2] + b0), h2, l2);
                bsplit(eluf(a4[3] + b1), h3, l3);
                if (mode == 0) {
                    if (row < M) {
                        *(__nv_bfloat162*)(CH + (size_t)row * ldc + col) = __nv_bfloat162(h0, h1);
                        *(__nv_bfloat162*)(CL + (size_t)row * ldc + col) = __nv_bfloat162(l0, l1);
                    }
                    if (row + 8 < M) {
                        *(__nv_bfloat162*)(CH + (size_t)(row + 8) * ldc + col) = __nv_bfloat162(h2, h3);
                        *(__nv_bfloat162*)(CL + (size_t)(row + 8) * ldc + col) = __nv_bfloat162(l2, l3);
                    }
                } else {  // mode 1: transposed
                    if (row < M) {
                        CH[(size_t)col * ldc + row] = h0;       CL[(size_t)col * ldc + row] = l0;
                        CH[(size_t)(col + 1) * ldc + row] = h1; CL[(size_t)(col + 1) * ldc + row] = l1;
                    }
                    if (row + 8 < M) {
                        CH[(size_t)col * ldc + row + 8] = h2;       CL[(size_t)col * ldc + row + 8] = l2;
                        CH[(size_t)(col + 1) * ldc + row + 8] = h3; CL[(size_t)(col + 1) * ldc + row + 8] = l3;
                    }
                }
            }
        }
    }
}

// =====================================================================
// split fp32 array -> bf16 hi/lo
// =====================================================================
__global__ void __launch_bounds__(256) split_arr(
    const float* __restrict__ src, bf16* __restrict__ hi,
    bf16* __restrict__ lo, int n)
{
    int i = blockIdx.x * 256 + threadIdx.x;
    if (i < n) {
        bf16 h, l;
        bsplit(src[i], h, l);
        hi[i] = h; lo[i] = l;
    }
}

// =====================================================================
// transpose H [B, d, L] -> Ht hi/lo [B, L, d] (bf16 pair)
// =====================================================================
__global__ void __launch_bounds__(256) transpose_hd(
    const float* __restrict__ H, bf16* __restrict__ Hthi, bf16* __restrict__ Htlo)
{
    __shared__ float tile[32][33];
    const int b  = blockIdx.z;
    const int l0 = blockIdx.x * 32, f0 = blockIdx.y * 32;
    const float* src = H + ((size_t)b * DD + f0) * LL + l0;
    for (int r = threadIdx.y; r < 32; r += 8)
        tile[r][threadIdx.x] = src[(size_t)r * LL + threadIdx.x];
    __syncthreads();
    size_t dbase = ((size_t)b * LL + l0) * DD + f0;
    for (int r = threadIdx.y; r < 32; r += 8) {
        bf16 h, l;
        bsplit(tile[threadIdx.x][r], h, l);
        Hthi[dbase + (size_t)r * DD + threadIdx.x] = h;
        Htlo[dbase + (size_t)r * DD + threadIdx.x] = l;
    }
}

// =====================================================================
// Row softmax (len 4096) -> bf16 hi/lo pair; optional fp32 writeback
// =====================================================================
__global__ void __launch_bounds__(256) softmax4096(
    float* __restrict__ X, bf16* __restrict__ Ohi, bf16* __restrict__ Olo,
    int write_f32)
{
    const size_t rb = (size_t)blockIdx.x * 4096;
    float* x = X + rb;
    const int tid = threadIdx.x;
    const int lane = tid & 31, wid = tid >> 5;
    __shared__ float red[32];

    float4 v[4];
    float mx = -1e30f;
    #pragma unroll
    for (int i = 0; i < 4; ++i) {
        v[i] = *(const float4*)&x[(i * 256 + tid) * 4];
        mx = fmaxf(mx, fmaxf(fmaxf(v[i].x, v[i].y), fmaxf(v[i].z, v[i].w)));
    }
    #pragma unroll
    for (int o = 16; o > 0; o >>= 1) mx = fmaxf(mx, __shfl_xor_sync(0xffffffffu, mx, o));
    if (lane == 0) red[wid] = mx;
    __syncthreads();
    if (wid == 0) {
        float m = (lane < 8) ? red[lane] : -1e30f;
        #pragma unroll
        for (int o = 4; o > 0; o >>= 1) m = fmaxf(m, __shfl_xor_sync(0xffffffffu, m, o));
        if (lane == 0) red[0] = m;
    }
    __syncthreads();
    mx = red[0];

    float sum = 0.0f;
    #pragma unroll
    for (int i = 0; i < 4; ++i) {
        v[i].x = __expf(v[i].x - mx);
        v[i].y = __expf(v[i].y - mx);
        v[i].z = __expf(v[i].z - mx);
        v[i].w = __expf(v[i].w - mx);
        sum += v[i].x + v[i].y + v[i].z + v[i].w;
    }
    #pragma unroll
    for (int o = 16; o > 0; o >>= 1) sum += __shfl_xor_sync(0xffffffffu, sum, o);
    if (lane == 0) red[16 + wid] = sum;
    __syncthreads();
    if (wid == 0) {
        float s = (lane < 8) ? red[16 + lane] : 0.0f;
        #pragma unroll
        for (int o = 4; o > 0; o >>= 1) s += __shfl_xor_sync(0xffffffffu, s, o);
        if (lane == 0) red[16] = s;
    }
    __syncthreads();
    const float inv = 1.0f / red[16];

    #pragma unroll
    for (int i = 0; i < 4; ++i) {
        const int e0 = (i * 256 + tid) * 4;
        v[i].x *= inv; v[i].y *= inv; v[i].z *= inv; v[i].w *= inv;
        if (write_f32) *(float4*)&x[e0] = v[i];
        bf16 h0, l0, h1, l1, h2, l2, h3, l3;
        bsplit(v[i].x, h0, l0); bsplit(v[i].y, h1, l1);
        bsplit(v[i].z, h2, l2); bsplit(v[i].w, h3, l3);
        *(__nv_bfloat162*)(Ohi + rb + e0)     = __nv_bfloat162(h0, h1);
        *(__nv_bfloat162*)(Ohi + rb + e0 + 2) = __nv_bfloat162(h2, h3);
        *(__nv_bfloat162*)(Olo + rb + e0)     = __nv_bfloat162(l0, l1);
        *(__nv_bfloat162*)(Olo + rb + e0 + 2) = __nv_bfloat162(l2, l3);
    }
}

// =====================================================================
// Q2b hi/lo = split(Q2[n,:] + C1[b, map[n], :])
// =====================================================================
__global__ void __launch_bounds__(128) q2b_kernel(
    const float* __restrict__ Q2, const int* __restrict__ cmap)
{
    const int n = blockIdx.x;
    const int b = blockIdx.y;
    const int c = cmap[n];
    const float4* q  = (const float4*)(Q2 + (size_t)n * DD);
    const float4* c1 = (const float4*)(g_C1 + ((size_t)b * NC1 + c) * DD);
    const size_t ob = ((size_t)b * NLBL + n) * DD;
    const int i = threadIdx.x;     // 128 threads, 4 elems each
    float4 a = q[i], bb = c1[i];
    float s0 = a.x + bb.x, s1 = a.y + bb.y, s2 = a.z + bb.z, s3 = a.w + bb.w;
    bf16 h0, l0, h1, l1, h2, l2, h3, l3;
    bsplit(s0, h0, l0); bsplit(s1, h1, l1); bsplit(s2, h2, l2); bsplit(s3, h3, l3);
    *(__nv_bfloat162*)(g_Q2bhi + ob + i * 4)     = __nv_bfloat162(h0, h1);
    *(__nv_bfloat162*)(g_Q2bhi + ob + i * 4 + 2) = __nv_bfloat162(h2, h3);
    *(__nv_bfloat162*)(g_Q2blo + ob + i * 4)     = __nv_bfloat162(l0, l1);
    *(__nv_bfloat162*)(g_Q2blo + ob + i * 4 + 2) = __nv_bfloat162(l2, l3);
}

// =====================================================================
// host
// =====================================================================
extern "C" void kernel_launch(void* const* d_in, const int* in_sizes, int n_in,
                              void* d_out, int out_size)
{
    const float* H    = (const float*)d_in[0];
    const float* Wk   = (const float*)d_in[1];
    const float* bk   = (const float*)d_in[2];
    const float* Wv   = (const float*)d_in[3];
    const float* bv   = (const float*)d_in[4];
    const float* Q1   = (const float*)d_in[5];
    const float* Q2   = (const float*)d_in[6];
    const int*   cmap = (const int*)d_in[7];

    float* C2 = (float*)d_out;                            // [B, Lbl, d]
    float* A2 = C2 + (size_t)BB * NLBL * DD;              // [B, Lbl, L]

    bf16 *pHth, *pHtl, *pKh, *pKl, *pVth, *pVtl, *pA1h, *pA1l;
    bf16 *pQ2bh, *pQ2bl, *pA2h, *pA2l, *pWkh, *pWkl, *pWvh, *pWvl, *pQ1h, *pQ1l;
    float *pE1, *pC1;
    cudaGetSymbolAddress((void**)&pHth,  g_Hthi);
    cudaGetSymbolAddress((void**)&pHtl,  g_Htlo);
    cudaGetSymbolAddress((void**)&pKh,   g_Khi);
    cudaGetSymbolAddress((void**)&pKl,   g_Klo);
    cudaGetSymbolAddress((void**)&pVth,  g_Vthi);
    cudaGetSymbolAddress((void**)&pVtl,  g_Vtlo);
    cudaGetSymbolAddress((void**)&pE1,   g_E1);
    cudaGetSymbolAddress((void**)&pA1h,  g_A1hi);
    cudaGetSymbolAddress((void**)&pA1l,  g_A1lo);
    cudaGetSymbolAddress((void**)&pC1,   g_C1);
    cudaGetSymbolAddress((void**)&pQ2bh, g_Q2bhi);
    cudaGetSymbolAddress((void**)&pQ2bl, g_Q2blo);
    cudaGetSymbolAddress((void**)&pA2h,  g_A2hi);
    cudaGetSymbolAddress((void**)&pA2l,  g_A2lo);
    cudaGetSymbolAddress((void**)&pWkh,  g_Wkhi);
    cudaGetSymbolAddress((void**)&pWkl,  g_Wklo);
    cudaGetSymbolAddress((void**)&pWvh,  g_Wvhi);
    cudaGetSymbolAddress((void**)&pWvl,  g_Wvlo);
    cudaGetSymbolAddress((void**)&pQ1h,  g_Q1hi);
    cudaGetSymbolAddress((void**)&pQ1l,  g_Q1lo);

    cudaFuncSetAttribute(gemm_tc, cudaFuncAttributeMaxDynamicSharedMemorySize, SM_TOTAL);

    // 0) split weights + Q1
    split_arr<<<(DD * DD + 255) / 256, 256>>>(Wk, pWkh, pWkl, DD * DD);
    split_arr<<<(DD * DD + 255) / 256, 256>>>(Wv, pWvh, pWvl, DD * DD);
    split_arr<<<(NC1 * DD + 255) / 256, 256>>>(Q1, pQ1h, pQ1l, NC1 * DD);

    // 1) Ht pair = transpose(H)
    transpose_hd<<<dim3(LL / 32, DD / 32, BB), dim3(32, 8)>>>(H, pHth, pHtl);

    // 2) K pair = split(elu(Ht Wk^T + bk))  [B,L,d]  (mode 0)
    gemm_tc<<<dim3(DD / 128, LL / 128, BB), 256, SM_TOTAL>>>(
        pHth, pHtl, pWkh, pWkl, (float*)0, pKh, pKl, bk,
        LL, DD, DD, DD, DD, (size_t)LL * DD, 0, (size_t)LL * DD, 1.0f, 0);

    // 3) Vt pair = split(elu(Ht Wv^T + bv))^T  [B,d,L]  (mode 1)
    gemm_tc<<<dim3(DD / 128, LL / 128, BB), 256, SM_TOTAL>>>(
        pHth, pHtl, pWvh, pWvl, (float*)0, pVth, pVtl, bv,
        LL, DD, DD, DD, LL, (size_t)LL * DD, 0, (size_t)DD * LL, 1.0f, 1);

    // 4) E1 = Q1 K^T / SCALE  [B,C1,L]  (mode 2)
    gemm_tc<<<dim3(LL / 128, (NC1 + 127) / 128, BB), 256, SM_TOTAL>>>(
        pQ1h, pQ1l, pKh, pKl, pE1, (bf16*)0, (bf16*)0, bk,
        NC1, DD, DD, DD, LL, 0, (size_t)LL * DD, (size_t)NC1 * LL, SCALE_INV, 2);

    // 5) softmax -> A1 pair (no fp32 writeback)
    softmax4096<<<BB * NC1, 256>>>(pE1, pA1h, pA1l, 0);

    // 6) C1 = A1 Vt^T  [B,C1,d]  (mode 2)
    gemm_tc<<<dim3(DD / 128, (NC1 + 127) / 128, BB), 256, SM_TOTAL>>>(
        pA1h, pA1l, pVth, pVtl, pC1, (bf16*)0, (bf16*)0, bk,
        NC1, LL, LL, LL, DD, (size_t)NC1 * LL, (size_t)DD * LL, (size_t)NC1 * DD, 1.0f, 2);

    // 7) Q2b pair = split(Q2 + C1[:, map, :])
    q2b_kernel<<<dim3(NLBL, BB), 128>>>(Q2, cmap);

    // 8) E2 = Q2b K^T / SCALE -> A2 (fp32 output region)  (mode 2)
    gemm_tc<<<dim3(LL / 128, (NLBL + 127) / 128, BB), 256, SM_TOTAL>>>(
        pQ2bh, pQ2bl, pKh, pKl, A2, (bf16*)0, (bf16*)0, bk,
        NLBL, DD, DD, DD, LL, (size_t)NLBL * DD, (size_t)LL * DD, (size_t)NLBL * LL, SCALE_INV, 2);

    // 9) softmax A2 (fp32 in place for output) + A2 pair for C2 GEMM
    softmax4096<<<BB * NLBL, 256>>>(A2, pA2h, pA2l, 1);

    // 10) C2 = A2 Vt^T  [B,Lbl,d]  (mode 2)
    gemm_tc<<<dim3(DD / 128, (NLBL + 127) / 128, BB), 256, SM_TOTAL>>>(
        pA2h, pA2l, pVth, pVtl, C2, (bf16*)0, (bf16*)0, bk,
        NLBL, LL, LL, LL, DD, (size_t)NLBL * LL, (size_t)DD * LL, (size_t)NLBL * DD, 1.0f, 2);
}

// round 7
// speedup vs baseline: 3.5442x; 1.0850x over previous
#include <cuda_runtime.h>
#include <cuda_bf16.h>
#include <math.h>
#include <stdint.h>

// Problem dims (fixed)
#define BB   4
#define DD   512
#define LL   4096
#define NC1  1168
#define NLBL 8929

#define SCALE_INV 0.044194173824159216f  // 1/sqrt(512)

#define KC 32   // K elements per chunk (bf16), 64B rows

// smem: 3-stage buffers, each tile 128x32 bf16 = 8KB
// AH: 0,8K,16K   AL: 24K+   BH: 48K+   BL: 72K+   total 96KB
#define S_AH 0
#define S_AL 24576
#define S_BH 49152
#define S_BL 73728
#define SM_TOTAL 98304

typedef __nv_bfloat16 bf16;

// ---------------- device scratch ----------------
__device__ bf16  g_Hthi [(size_t)BB * LL * DD];
__device__ bf16  g_Htlo [(size_t)BB * LL * DD];
__device__ bf16  g_Khi  [(size_t)BB * LL * DD];     // [B, L, d]
__device__ bf16  g_Klo  [(size_t)BB * LL * DD];
__device__ bf16  g_Vthi [(size_t)BB * DD * LL];     // [B, d, L]
__device__ bf16  g_Vtlo [(size_t)BB * DD * LL];
__device__ float g_E1   [(size_t)BB * NC1 * LL];    // [B, C1, L]
__device__ bf16  g_A1hi [(size_t)BB * NC1 * LL];
__device__ bf16  g_A1lo [(size_t)BB * NC1 * LL];
__device__ float g_C1   [(size_t)BB * NC1 * DD];    // [B, C1, d]
__device__ bf16  g_Q2bhi[(size_t)BB * NLBL * DD];
__device__ bf16  g_Q2blo[(size_t)BB * NLBL * DD];
__device__ bf16  g_A2hi [(size_t)BB * NLBL * LL];
__device__ bf16  g_A2lo [(size_t)BB * NLBL * LL];
__device__ bf16  g_Wkhi [(size_t)DD * DD];
__device__ bf16  g_Wklo [(size_t)DD * DD];
__device__ bf16  g_Wvhi [(size_t)DD * DD];
__device__ bf16  g_Wvlo [(size_t)DD * DD];
__device__ bf16  g_Q1hi [(size_t)NC1 * DD];
__device__ bf16  g_Q1lo [(size_t)NC1 * DD];

// ---------------- helpers ----------------
__device__ __forceinline__ uint32_t smem_u32(const void* p) {
    uint32_t a;
    asm("{ .reg .u64 t; cvta.to.shared.u64 t, %1; cvt.u32.u64 %0, t; }" : "=r"(a) : "l"(p));
    return a;
}
__device__ __forceinline__ void cp16(uint32_t dst, const void* src, bool pred) {
    int sz = pred ? 16 : 0;
    asm volatile("cp.async.cg.shared.global [%0], [%1], 16, %2;"
                 :: "r"(dst), "l"(src), "r"(sz));
}
__device__ __forceinline__ void cp_commit() {
    asm volatile("cp.async.commit_group;" ::: "memory");
}
__device__ __forceinline__ void ldsm4(uint32_t* r, uint32_t addr) {
    asm volatile("ldmatrix.sync.aligned.m8n8.x4.shared.b16 {%0,%1,%2,%3}, [%4];"
                 : "=r"(r[0]), "=r"(r[1]), "=r"(r[2]), "=r"(r[3]) : "r"(addr));
}
__device__ __forceinline__ void mma_bf16(float* d, const uint32_t* a, const uint32_t* b) {
    asm volatile(
        "mma.sync.aligned.m16n8k16.row.col.f32.bf16.bf16.f32 "
        "{%0,%1,%2,%3}, {%4,%5,%6,%7}, {%8,%9}, {%0,%1,%2,%3};"
        : "+f"(d[0]), "+f"(d[1]), "+f"(d[2]), "+f"(d[3])
        : "r"(a[0]), "r"(a[1]), "r"(a[2]), "r"(a[3]), "r"(b[0]), "r"(b[1]));
}
__device__ __forceinline__ void bsplit(float x, bf16& h, bf16& l) {
    h = __float2bfloat16_rn(x);
    l = __float2bfloat16_rn(x - __bfloat162float(h));
}
__device__ __forceinline__ float eluf(float x) { return x > 0.0f ? x : expm1f(x); }

// =====================================================================
// 3xBF16 mma.sync NT GEMM, 3-stage cp.async pipeline (1 barrier/chunk).
// D[m,n] = sum_k A[m,k]*B[n,k]; A,B pre-split bf16 hi/lo, K-major.
// mode 0: split(elu(acc+bias[n])) -> Chi/Clo[m*ldc+n]  (bf16)
// mode 1: split(elu(acc+bias[n])) -> Chi/Clo[n*ldc+m]  (bf16, transposed)
// mode 2: Cf[m*ldc+n] = alpha * acc                     (fp32)
// N, K multiples of 128 / 32; M may be ragged.
// =====================================================================
__global__ void __launch_bounds__(256, 2) gemm_tc(
    const bf16* __restrict__ Ahi, const bf16* __restrict__ Alo,
    const bf16* __restrict__ Bhi, const bf16* __restrict__ Blo,
    float* __restrict__ Cf, bf16* __restrict__ Chi, bf16* __restrict__ Clo,
    const float* __restrict__ bias,
    int M, int K, int lda, int ldb, int ldc,
    size_t sA, size_t sB, size_t sC, float alpha, int mode)
{
    extern __shared__ char smem[];
    const uint32_t sbase = smem_u32(smem);

    const int tid  = threadIdx.x;
    const int wid  = tid >> 5;
    const int lane = tid & 31;
    const int g    = lane >> 3;
    const int r    = lane & 7;
    const int warp_m = wid & 3;
    const int warp_n = wid >> 2;

    const bf16* Ah = Ahi + (size_t)blockIdx.z * sA;
    const bf16* Al = Alo + (size_t)blockIdx.z * sA;
    const bf16* Bh = Bhi + (size_t)blockIdx.z * sB;
    const bf16* Bl = Blo + (size_t)blockIdx.z * sB;
    const int m0 = blockIdx.y * 128;
    const int n0 = blockIdx.x * 128;

    // ldmatrix offsets within a tile (64B rows; swizzle: quad ^= (row>>1)&3)
    uint32_t aoff[2], aswz[2], boff[4], bswz[4];
    #pragma unroll
    for (int mt = 0; mt < 2; ++mt) {
        int row = warp_m * 32 + mt * 16 + (g & 1) * 8 + r;
        aoff[mt] = (uint32_t)row * 64;
        aswz[mt] = (uint32_t)((row >> 1) & 3);
    }
    const uint32_t aq = (uint32_t)(g >> 1);
    #pragma unroll
    for (int p = 0; p < 4; ++p) {
        int row = warp_n * 64 + p * 16 + (g >> 1) * 8 + r;
        boff[p] = (uint32_t)row * 64;
        bswz[p] = (uint32_t)((row >> 1) & 3);
    }
    const uint32_t bq = (uint32_t)(g & 1);

    // cp.async staging: 2 rows per thread per tile
    const int sr0 = tid >> 2;
    const int sq  = tid & 3;

    float acc[2][8][4];
    #pragma unroll
    for (int mt = 0; mt < 2; ++mt)
        #pragma unroll
        for (int nt = 0; nt < 8; ++nt)
            #pragma unroll
            for (int c = 0; c < 4; ++c) acc[mt][nt][c] = 0.0f;

    const int nc = K >> 5;

#define STAGE(BUF, K0)                                                           \
    {                                                                            \
        const uint32_t _bo = (uint32_t)(BUF) * 8192u;                            \
        _Pragma("unroll")                                                        \
        for (int q = 0; q < 2; ++q) {                                            \
            int row = sr0 + q * 64;                                              \
            uint32_t d = (uint32_t)row * 64 + ((sq ^ ((row >> 1) & 3)) << 4);    \
            int m = m0 + row;                                                    \
            size_t ao = (size_t)(m < M ? m : 0) * lda + (K0) + sq * 8;           \
            cp16(sbase + S_AH + _bo + d, Ah + ao, m < M);                        \
            cp16(sbase + S_AL + _bo + d, Al + ao, m < M);                        \
            size_t bo2 = (size_t)(n0 + row) * ldb + (K0) + sq * 8;               \
            cp16(sbase + S_BH + _bo + d, Bh + bo2, true);                        \
            cp16(sbase + S_BL + _bo + d, Bl + bo2, true);                        \
        }                                                                        \
        cp_commit();                                                             \
    }

    STAGE(0, 0)
    STAGE(1, KC)

    int bi = 0;
    for (int i = 0; i < nc; ++i) {
        asm volatile("cp.async.wait_group 1;" ::: "memory");
        __syncthreads();

        const uint32_t bo  = (uint32_t)bi * 8192u;
        const uint32_t ahb = sbase + S_AH + bo;
        const uint32_t alb = sbase + S_AL + bo;
        const uint32_t bhb = sbase + S_BH + bo;
        const uint32_t blb = sbase + S_BL + bo;

        #pragma unroll
        for (int ks = 0; ks < 2; ++ks) {
            const uint32_t qa = (uint32_t)(ks * 2) + aq;
            const uint32_t qb = (uint32_t)(ks * 2) + bq;
            uint32_t ah[2][4], al[2][4];
            #pragma unroll
            for (int mt = 0; mt < 2; ++mt) {
                const uint32_t o = aoff[mt] + ((qa ^ aswz[mt]) << 4);
                ldsm4(ah[mt], ahb + o);
                ldsm4(al[mt], alb + o);
            }
            #pragma unroll
            for (int p = 0; p < 4; ++p) {
                uint32_t bhf[4], blf[4];
                const uint32_t o = boff[p] + ((qb ^ bswz[p]) << 4);
                ldsm4(bhf, bhb + o);
                ldsm4(blf, blb + o);
                #pragma unroll
                for (int h2 = 0; h2 < 2; ++h2) {
                    const int nt = p * 2 + h2;
                    #pragma unroll
                    for (int mt = 0; mt < 2; ++mt) {
                        mma_bf16(acc[mt][nt], ah[mt], &bhf[h2 * 2]);  // hi*hi
                        mma_bf16(acc[mt][nt], ah[mt], &blf[h2 * 2]);  // hi*lo
                        mma_bf16(acc[mt][nt], al[mt], &bhf[h2 * 2]);  // lo*hi
                    }
                }
            }
        }

        // stage chunk i+2 into the buffer freed at iteration i-1
        if (i + 2 < nc) {
            int nb = bi + 2; if (nb >= 3) nb -= 3;
            const int k0 = (i + 2) * KC;
            STAGE(nb, k0)
        } else {
            cp_commit();   // empty group keeps wait_group accounting exact
        }
        if (++bi == 3) bi = 0;
    }
#undef STAGE

    // ---- epilogue ----
    const int rq = lane >> 2;
    const int cq = (lane & 3) * 2;
    float* C  = Cf  ? Cf  + (size_t)blockIdx.z * sC : (float*)0;
    bf16*  CH = Chi ? Chi + (size_t)blockIdx.z * sC : (bf16*)0;
    bf16*  CL = Clo ? Clo + (size_t)blockIdx.z * sC : (bf16*)0;
    #pragma unroll
    for (int mt = 0; mt < 2; ++mt) {
        #pragma unroll
        for (int nt = 0; nt < 8; ++nt) {
            const int row = m0 + warp_m * 32 + mt * 16 + rq;
            const int col = n0 + warp_n * 64 + nt * 8 + cq;
            const float* a4 = acc[mt][nt];
            if (mode == 2) {
                if (row < M)
                    *(float2*)(C + (size_t)row * ldc + col) =
                        make_float2(alpha * a4[0], alpha * a4[1]);
                if (row + 8 < M)
                    *(float2*)(C + (size_t)(row + 8) * ldc + col) =
                        make_float2(alpha * a4[2], alpha * a4[3]);
            } else {
                const float b0 = bias[col], b1 = bias[col + 1];
                bf16 h0, l0, h1, l1, h2, l2, h3, l3;
                bsplit(eluf(a4[0] + b0), h0, l0);
                bsplit(eluf(a4[1] + b1), h1, l1);
                bsplit(eluf(a4[2] + b0), h2, l2);
                bsplit(eluf(a4[3] + b1), h3, l3);
                if (mode == 0) {
                    if (row < M) {
                        *(__nv_bfloat162*)(CH + (size_t)row * ldc + col) = __nv_bfloat162(h0, h1);
                        *(__nv_bfloat162*)(CL + (size_t)row * ldc + col) = __nv_bfloat162(l0, l1);
                    }
                    if (row + 8 < M) {
                        *(__nv_bfloat162*)(CH + (size_t)(row + 8) * ldc + col) = __nv_bfloat162(h2, h3);
                        *(__nv_bfloat162*)(CL + (size_t)(row + 8) * ldc + col) = __nv_bfloat162(l2, l3);
                    }
                } else {  // mode 1: transposed
                    if (row < M) {
                        CH[(size_t)col * ldc + row] = h0;       CL[(size_t)col * ldc + row] = l0;
                        CH[(size_t)(col + 1) * ldc + row] = h1; CL[(size_t)(col + 1) * ldc + row] = l1;
                    }
                    if (row + 8 < M) {
                        CH[(size_t)col * ldc + row + 8] = h2;       CL[(size_t)col * ldc + row + 8] = l2;
                        CH[(size_t)(col + 1) * ldc + row + 8] = h3; CL[(size_t)(col + 1) * ldc + row + 8] = l3;
                    }
                }
            }
        }
    }
}

// =====================================================================
// split fp32 array -> bf16 hi/lo
// =====================================================================
__global__ void __launch_bounds__(256) split_arr(
    const float* __restrict__ src, bf16* __restrict__ hi,
    bf16* __restrict__ lo, int n)
{
    int i = blockIdx.x * 256 + threadIdx.x;
    if (i < n) {
        bf16 h, l;
        bsplit(src[i], h, l);
        hi[i] = h; lo[i] = l;
    }
}

// =====================================================================
// transpose H [B, d, L] -> Ht hi/lo [B, L, d] (bf16 pair)
// =====================================================================
__global__ void __launch_bounds__(256) transpose_hd(
    const float* __restrict__ H, bf16* __restrict__ Hthi, bf16* __restrict__ Htlo)
{
    __shared__ float tile[32][33];
    const int b  = blockIdx.z;
    const int l0 = blockIdx.x * 32, f0 = blockIdx.y * 32;
    const float* src = H + ((size_t)b * DD + f0) * LL + l0;
    for (int r = threadIdx.y; r < 32; r += 8)
        tile[r][threadIdx.x] = src[(size_t)r * LL + threadIdx.x];
    __syncthreads();
    size_t dbase = ((size_t)b * LL + l0) * DD + f0;
    for (int r = threadIdx.y; r < 32; r += 8) {
        bf16 h, l;
        bsplit(tile[threadIdx.x][r], h, l);
        Hthi[dbase + (size_t)r * DD + threadIdx.x] = h;
        Htlo[dbase + (size_t)r * DD + threadIdx.x] = l;
    }
}

// =====================================================================
// Row softmax (len 4096) -> bf16 hi/lo pair; optional fp32 writeback
// =====================================================================
__global__ void __launch_bounds__(256) softmax4096(
    float* __restrict__ X, bf16* __restrict__ Ohi, bf16* __restrict__ Olo,
    int write_f32)
{
    const size_t rb = (size_t)blockIdx.x * 4096;
    float* x = X + rb;
    const int tid = threadIdx.x;
    const int lane = tid & 31, wid = tid >> 5;
    __shared__ float red[32];

    float4 v[4];
    float mx = -1e30f;
    #pragma unroll
    for (int i = 0; i < 4; ++i) {
        v[i] = *(const float4*)&x[(i * 256 + tid) * 4];
        mx = fmaxf(mx, fmaxf(fmaxf(v[i].x, v[i].y), fmaxf(v[i].z, v[i].w)));
    }
    #pragma unroll
    for (int o = 16; o > 0; o >>= 1) mx = fmaxf(mx, __shfl_xor_sync(0xffffffffu, mx, o));
    if (lane == 0) red[wid] = mx;
    __syncthreads();
    if (wid == 0) {
        float m = (lane < 8) ? red[lane] : -1e30f;
        #pragma unroll
        for (int o = 4; o > 0; o >>= 1) m = fmaxf(m, __shfl_xor_sync(0xffffffffu, m, o));
        if (lane == 0) red[0] = m;
    }
    __syncthreads();
    mx = red[0];

    float sum = 0.0f;
    #pragma unroll
    for (int i = 0; i < 4; ++i) {
        v[i].x = __expf(v[i].x - mx);
        v[i].y = __expf(v[i].y - mx);
        v[i].z = __expf(v[i].z - mx);
        v[i].w = __expf(v[i].w - mx);
        sum += v[i].x + v[i].y + v[i].z + v[i].w;
    }
    #pragma unroll
    for (int o = 16; o > 0; o >>= 1) sum += __shfl_xor_sync(0xffffffffu, sum, o);
    if (lane == 0) red[16 + wid] = sum;
    __syncthreads();
    if (wid == 0) {
        float s = (lane < 8) ? red[16 + lane] : 0.0f;
        #pragma unroll
        for (int o = 4; o > 0; o >>= 1) s += __shfl_xor_sync(0xffffffffu, s, o);
        if (lane == 0) red[16] = s;
    }
    __syncthreads();
    const float inv = 1.0f / red[16];

    #pragma unroll
    for (int i = 0; i < 4; ++i) {
        const int e0 = (i * 256 + tid) * 4;
        v[i].x *= inv; v[i].y *= inv; v[i].z *= inv; v[i].w *= inv;
        if (write_f32) *(float4*)&x[e0] = v[i];
        bf16 h0, l0, h1, l1, h2, l2, h3, l3;
        bsplit(v[i].x, h0, l0); bsplit(v[i].y, h1, l1);
        bsplit(v[i].z, h2, l2); bsplit(v[i].w, h3, l3);
        *(__nv_bfloat162*)(Ohi + rb + e0)     = __nv_bfloat162(h0, h1);
        *(__nv_bfloat162*)(Ohi + rb + e0 + 2) = __nv_bfloat162(h2, h3);
        *(__nv_bfloat162*)(Olo + rb + e0)     = __nv_bfloat162(l0, l1);
        *(__nv_bfloat162*)(Olo + rb + e0 + 2) = __nv_bfloat162(l2, l3);
    }
}

// =====================================================================
// Q2b hi/lo = split(Q2[n,:] + C1[b, map[n], :])
// =====================================================================
__global__ void __launch_bounds__(128) q2b_kernel(
    const float* __restrict__ Q2, const int* __restrict__ cmap)
{
    const int n = blockIdx.x;
    const int b = blockIdx.y;
    const int c = cmap[n];
    const float4* q  = (const float4*)(Q2 + (size_t)n * DD);
    const float4* c1 = (const float4*)(g_C1 + ((size_t)b * NC1 + c) * DD);
    const size_t ob = ((size_t)b * NLBL + n) * DD;
    const int i = threadIdx.x;
    float4 a = q[i], bb = c1[i];
    float s0 = a.x + bb.x, s1 = a.y + bb.y, s2 = a.z + bb.z, s3 = a.w + bb.w;
    bf16 h0, l0, h1, l1, h2, l2, h3, l3;
    bsplit(s0, h0, l0); bsplit(s1, h1, l1); bsplit(s2, h2, l2); bsplit(s3, h3, l3);
    *(__nv_bfloat162*)(g_Q2bhi + ob + i * 4)     = __nv_bfloat162(h0, h1);
    *(__nv_bfloat162*)(g_Q2bhi + ob + i * 4 + 2) = __nv_bfloat162(h2, h3);
    *(__nv_bfloat162*)(g_Q2blo + ob + i * 4)     = __nv_bfloat162(l0, l1);
    *(__nv_bfloat162*)(g_Q2blo + ob + i * 4 + 2) = __nv_bfloat162(l2, l3);
}

// =====================================================================
// host
// =====================================================================
extern "C" void kernel_launch(void* const* d_in, const int* in_sizes, int n_in,
                              void* d_out, int out_size)
{
    const float* H    = (const float*)d_in[0];
    const float* Wk   = (const float*)d_in[1];
    const float* bk   = (const float*)d_in[2];
    const float* Wv   = (const float*)d_in[3];
    const float* bv   = (const float*)d_in[4];
    const float* Q1   = (const float*)d_in[5];
    const float* Q2   = (const float*)d_in[6];
    const int*   cmap = (const int*)d_in[7];

    float* C2 = (float*)d_out;                            // [B, Lbl, d]
    float* A2 = C2 + (size_t)BB * NLBL * DD;              // [B, Lbl, L]

    bf16 *pHth, *pHtl, *pKh, *pKl, *pVth, *pVtl, *pA1h, *pA1l;
    bf16 *pQ2bh, *pQ2bl, *pA2h, *pA2l, *pWkh, *pWkl, *pWvh, *pWvl, *pQ1h, *pQ1l;
    float *pE1, *pC1;
    cudaGetSymbolAddress((void**)&pHth,  g_Hthi);
    cudaGetSymbolAddress((void**)&pHtl,  g_Htlo);
    cudaGetSymbolAddress((void**)&pKh,   g_Khi);
    cudaGetSymbolAddress((void**)&pKl,   g_Klo);
    cudaGetSymbolAddress((void**)&pVth,  g_Vthi);
    cudaGetSymbolAddress((void**)&pVtl,  g_Vtlo);
    cudaGetSymbolAddress((void**)&pE1,   g_E1);
    cudaGetSymbolAddress((void**)&pA1h,  g_A1hi);
    cudaGetSymbolAddress((void**)&pA1l,  g_A1lo);
    cudaGetSymbolAddress((void**)&pC1,   g_C1);
    cudaGetSymbolAddress((void**)&pQ2bh, g_Q2bhi);
    cudaGetSymbolAddress((void**)&pQ2bl, g_Q2blo);
    cudaGetSymbolAddress((void**)&pA2h,  g_A2hi);
    cudaGetSymbolAddress((void**)&pA2l,  g_A2lo);
    cudaGetSymbolAddress((void**)&pWkh,  g_Wkhi);
    cudaGetSymbolAddress((void**)&pWkl,  g_Wklo);
    cudaGetSymbolAddress((void**)&pWvh,  g_Wvhi);
    cudaGetSymbolAddress((void**)&pWvl,  g_Wvlo);
    cudaGetSymbolAddress((void**)&pQ1h,  g_Q1hi);
    cudaGetSymbolAddress((void**)&pQ1l,  g_Q1lo);

    cudaFuncSetAttribute(gemm_tc, cudaFuncAttributeMaxDynamicSharedMemorySize, SM_TOTAL);

    // 0) split weights + Q1
    split_arr<<<(DD * DD + 255) / 256, 256>>>(Wk, pWkh, pWkl, DD * DD);
    split_arr<<<(DD * DD + 255) / 256, 256>>>(Wv, pWvh, pWvl, DD * DD);
    split_arr<<<(NC1 * DD + 255) / 256, 256>>>(Q1, pQ1h, pQ1l, NC1 * DD);

    // 1) Ht pair = transpose(H)
    transpose_hd<<<dim3(LL / 32, DD / 32, BB), dim3(32, 8)>>>(H, pHth, pHtl);

    // 2) K pair = split(elu(Ht Wk^T + bk))  [B,L,d]  (mode 0)
    gemm_tc<<<dim3(DD / 128, LL / 128, BB), 256, SM_TOTAL>>>(
        pHth, pHtl, pWkh, pWkl, (float*)0, pKh, pKl, bk,
        LL, DD, DD, DD, DD, (size_t)LL * DD, 0, (size_t)LL * DD, 1.0f, 0);

    // 3) Vt pair = split(elu(Ht Wv^T + bv))^T  [B,d,L]  (mode 1)
    gemm_tc<<<dim3(DD / 128, LL / 128, BB), 256, SM_TOTAL>>>(
        pHth, pHtl, pWvh, pWvl, (float*)0, pVth, pVtl, bv,
        LL, DD, DD, DD, LL, (size_t)LL * DD, 0, (size_t)DD * LL, 1.0f, 1);

    // 4) E1 = Q1 K^T / SCALE  [B,C1,L]  (mode 2)
    gemm_tc<<<dim3(LL / 128, (NC1 + 127) / 128, BB), 256, SM_TOTAL>>>(
        pQ1h, pQ1l, pKh, pKl, pE1, (bf16*)0, (bf16*)0, bk,
        NC1, DD, DD, DD, LL, 0, (size_t)LL * DD, (size_t)NC1 * LL, SCALE_INV, 2);

    // 5) softmax -> A1 pair
    softmax4096<<<BB * NC1, 256>>>(pE1, pA1h, pA1l, 0);

    // 6) C1 = A1 Vt^T  [B,C1,d]  (mode 2)
    gemm_tc<<<dim3(DD / 128, (NC1 + 127) / 128, BB), 256, SM_TOTAL>>>(
        pA1h, pA1l, pVth, pVtl, pC1, (bf16*)0, (bf16*)0, bk,
        NC1, LL, LL, LL, DD, (size_t)NC1 * LL, (size_t)DD * LL, (size_t)NC1 * DD, 1.0f, 2);

    // 7) Q2b pair = split(Q2 + C1[:, map, :])
    q2b_kernel<<<dim3(NLBL, BB), 128>>>(Q2, cmap);

    // 8) E2 = Q2b K^T / SCALE -> A2 (fp32 output region)  (mode 2)
    gemm_tc<<<dim3(LL / 128, (NLBL + 127) / 128, BB), 256, SM_TOTAL>>>(
        pQ2bh, pQ2bl, pKh, pKl, A2, (bf16*)0, (bf16*)0, bk,
        NLBL, DD, DD, DD, LL, (size_t)NLBL * DD, (size_t)LL * DD, (size_t)NLBL * LL, SCALE_INV, 2);

    // 9) softmax A2 (fp32 in place for output) + A2 pair for C2 GEMM
    softmax4096<<<BB * NLBL, 256>>>(A2, pA2h, pA2l, 1);

    // 10) C2 = A2 Vt^T  [B,Lbl,d]  (mode 2)
    gemm_tc<<<dim3(DD / 128, (NLBL + 127) / 128, BB), 256, SM_TOTAL>>>(
        pA2h, pA2l, pVth, pVtl, C2, (bf16*)0, (bf16*)0, bk,
        NLBL, LL, LL, LL, DD, (size_t)NLBL * LL, (size_t)DD * LL, (size_t)NLBL * DD, 1.0f, 2);
}